// round 1
// baseline (speedup 1.0000x reference)
#include <cuda_runtime.h>
#include <cstdint>

#define SEQ    197
#define BATCH  64
#define HID    768
#define NHEAD  12
#define HD     64
#define MTOT   (BATCH*SEQ)      // 12608
#define NUMREL 732              // (2*14-1)^2 + 3

// ---------------- scratch (module-static device memory; no runtime alloc) ----
__device__ float g_q[MTOT*HID];
__device__ float g_k[MTOT*HID];
__device__ float g_v[MTOT*HID];
__device__ float g_bias[NHEAD*SEQ*SEQ];

// ---------------- helpers ----------------------------------------------------
__device__ __forceinline__ uint32_t f2tf(float f){
    uint32_t u; asm("cvt.rna.tf32.f32 %0, %1;" : "=r"(u) : "f"(f)); return u;
}

__device__ __forceinline__ void mma8(float* d, const uint32_t* a, const uint32_t* b){
    asm volatile("mma.sync.aligned.m16n8k8.row.col.f32.tf32.tf32.f32 "
        "{%0,%1,%2,%3}, {%4,%5,%6,%7}, {%8,%9}, {%0,%1,%2,%3};"
        : "+f"(d[0]), "+f"(d[1]), "+f"(d[2]), "+f"(d[3])
        : "r"(a[0]), "r"(a[1]), "r"(a[2]), "r"(a[3]), "r"(b[0]), "r"(b[1]));
}

// ---------------- QKV projection GEMM (tf32 tensor cores) --------------------
// C[M=12608, N=768] = A[12608,768] @ W[768,768] (+ bias)
#define BM 128
#define BN 64
#define BK 32

__global__ __launch_bounds__(256) void qkv_gemm(const float* __restrict__ A,
                                                const float* __restrict__ W,
                                                const float* __restrict__ bias,
                                                float* __restrict__ C){
    __shared__ float As[BM][BK+4];
    __shared__ float Ws[BK][BN+8];
    const int bm = blockIdx.x * BM, bn = blockIdx.y * BN;
    const int tid = threadIdx.x, wid = tid >> 5, lane = tid & 31;
    const int wm = (wid & 3) * 32;   // 4 warps tile M
    const int wn = (wid >> 2) * 32;  // 2 warps tile N
    const int g  = lane >> 2, tg = lane & 3;

    float acc[2][4][4];
    #pragma unroll
    for(int i=0;i<2;i++)
        #pragma unroll
        for(int j=0;j<4;j++)
            #pragma unroll
            for(int r=0;r<4;r++) acc[i][j][r] = 0.f;

    for(int k0 = 0; k0 < HID; k0 += BK){
        // stage A tile: 128x32 fp32 -> tf32 bits
        #pragma unroll
        for(int i=0;i<4;i++){
            int v = tid + i*256;
            int r = v >> 3, c = (v & 7) * 4;
            int grow = bm + r;
            float4 val = make_float4(0.f,0.f,0.f,0.f);
            if(grow < MTOT) val = *(const float4*)(A + (size_t)grow*HID + k0 + c);
            As[r][c+0] = __uint_as_float(f2tf(val.x));
            As[r][c+1] = __uint_as_float(f2tf(val.y));
            As[r][c+2] = __uint_as_float(f2tf(val.z));
            As[r][c+3] = __uint_as_float(f2tf(val.w));
        }
        // stage W tile: 32x64
        #pragma unroll
        for(int i=0;i<2;i++){
            int v = tid + i*256;
            int r = v >> 4, c = (v & 15) * 4;
            float4 val = *(const float4*)(W + (size_t)(k0+r)*HID + bn + c);
            Ws[r][c+0] = __uint_as_float(f2tf(val.x));
            Ws[r][c+1] = __uint_as_float(f2tf(val.y));
            Ws[r][c+2] = __uint_as_float(f2tf(val.z));
            Ws[r][c+3] = __uint_as_float(f2tf(val.w));
        }
        __syncthreads();

        #pragma unroll
        for(int kk = 0; kk < BK; kk += 8){
            uint32_t af[2][4], bf[4][2];
            #pragma unroll
            for(int mi=0;mi<2;mi++){
                int r = wm + mi*16 + g;
                af[mi][0] = __float_as_uint(As[r  ][kk+tg  ]);
                af[mi][1] = __float_as_uint(As[r+8][kk+tg  ]);
                af[mi][2] = __float_as_uint(As[r  ][kk+tg+4]);
                af[mi][3] = __float_as_uint(As[r+8][kk+tg+4]);
            }
            #pragma unroll
            for(int ni=0;ni<4;ni++){
                int c = wn + ni*8 + g;
                bf[ni][0] = __float_as_uint(Ws[kk+tg  ][c]);
                bf[ni][1] = __float_as_uint(Ws[kk+tg+4][c]);
            }
            #pragma unroll
            for(int mi=0;mi<2;mi++)
                #pragma unroll
                for(int ni=0;ni<4;ni++)
                    mma8(acc[mi][ni], af[mi], bf[ni]);
        }
        __syncthreads();
    }

    // epilogue: bias add + store
    #pragma unroll
    for(int mi=0;mi<2;mi++){
        #pragma unroll
        for(int ni=0;ni<4;ni++){
            int col = bn + wn + ni*8 + tg*2;
            float b0 = bias ? bias[col]   : 0.f;
            float b1 = bias ? bias[col+1] : 0.f;
            int r0 = bm + wm + mi*16 + g;
            if(r0 < MTOT){
                C[(size_t)r0*HID+col]   = acc[mi][ni][0] + b0;
                C[(size_t)r0*HID+col+1] = acc[mi][ni][1] + b1;
            }
            int r1 = r0 + 8;
            if(r1 < MTOT){
                C[(size_t)r1*HID+col]   = acc[mi][ni][2] + b0;
                C[(size_t)r1*HID+col+1] = acc[mi][ni][3] + b1;
            }
        }
    }
}

// ---------------- relative position bias build --------------------------------
__global__ void build_bias(const float* __restrict__ table, float* __restrict__ bias){
    int qk = blockIdx.x * blockDim.x + threadIdx.x;
    if(qk >= SEQ*SEQ) return;
    int q = qk / SEQ, k = qk % SEQ;
    int idx;
    if(q == 0 && k == 0)      idx = NUMREL - 1;   // 731
    else if(q == 0)           idx = NUMREL - 3;   // 729
    else if(k == 0)           idx = NUMREL - 2;   // 730
    else {
        int i = q - 1, j = k - 1;
        int hi = i / 14, wi = i % 14;
        int hj = j / 14, wj = j % 14;
        idx = (hi - hj + 13) * 27 + (wi - wj + 13);
    }
    #pragma unroll
    for(int h = 0; h < NHEAD; h++)
        bias[h*SEQ*SEQ + qk] = table[idx*NHEAD + h];
}

// ---------------- attention: one block per (batch, head) -----------------------
// smem: K [197][65], V [197][65] (pad 65 -> conflict-free column access)
__global__ __launch_bounds__(256) void attention(const float* __restrict__ Q,
                                                 const float* __restrict__ K,
                                                 const float* __restrict__ V,
                                                 const float* __restrict__ bias,
                                                 float* __restrict__ out){
    extern __shared__ float kvsh[];
    float* Ks = kvsh;               // SEQ*65
    float* Vs = kvsh + SEQ*65;
    __shared__ float Ps[8][SEQ+3];

    const int b = blockIdx.x / NHEAD, h = blockIdx.x % NHEAD;
    const int tid = threadIdx.x, wid = tid >> 5, lane = tid & 31;

    const float* Kb = K + (size_t)(b*SEQ)*HID + h*HD;
    const float* Vb = V + (size_t)(b*SEQ)*HID + h*HD;

    for(int v = tid; v < SEQ*16; v += 256){
        int s = v >> 4, d = (v & 15) * 4;
        float4 kk = *(const float4*)(Kb + (size_t)s*HID + d);
        Ks[s*65+d]   = kk.x; Ks[s*65+d+1] = kk.y;
        Ks[s*65+d+2] = kk.z; Ks[s*65+d+3] = kk.w;
        float4 vv = *(const float4*)(Vb + (size_t)s*HID + d);
        Vs[s*65+d]   = vv.x; Vs[s*65+d+1] = vv.y;
        Vs[s*65+d+2] = vv.z; Vs[s*65+d+3] = vv.w;
    }
    __syncthreads();

    const float* biash = bias + (size_t)h*SEQ*SEQ;
    const float* Qb    = Q + (size_t)(b*SEQ)*HID + h*HD;

    for(int q = wid; q < SEQ; q += 8){
        // q row into registers (broadcast loads, L1-resident)
        float qr[HD];
        const float* qrow = Qb + (size_t)q*HID;
        #pragma unroll
        for(int d=0; d<HD; d++) qr[d] = qrow[d] * 0.125f;   // 1/sqrt(64)

        // scores: lane handles k = lane + 32*j
        float sc[7];
        float m = -1e30f;
        #pragma unroll
        for(int j=0;j<7;j++){
            int k = lane + j*32;
            float dot = -1e30f;
            if(k < SEQ){
                const float* krow = Ks + k*65;
                dot = 0.f;
                #pragma unroll
                for(int d=0; d<HD; d++) dot += qr[d] * krow[d];
                dot += biash[q*SEQ + k];
            }
            sc[j] = dot;
            m = fmaxf(m, dot);
        }
        #pragma unroll
        for(int o=16;o;o>>=1) m = fmaxf(m, __shfl_xor_sync(0xffffffffu, m, o));

        float sum = 0.f;
        #pragma unroll
        for(int j=0;j<7;j++){
            float e = __expf(sc[j] - m);
            if(lane + j*32 >= SEQ) e = 0.f;
            sc[j] = e;
            sum += e;
        }
        #pragma unroll
        for(int o=16;o;o>>=1) sum += __shfl_xor_sync(0xffffffffu, sum, o);
        float inv = 1.0f / sum;

        #pragma unroll
        for(int j=0;j<7;j++){
            int k = lane + j*32;
            if(k < SEQ) Ps[wid][k] = sc[j] * inv;
        }
        __syncwarp();

        // PV: lane owns output dims lane and lane+32
        float o0 = 0.f, o1 = 0.f;
        for(int k=0;k<SEQ;k++){
            float p = Ps[wid][k];
            o0 += p * Vs[k*65 + lane];
            o1 += p * Vs[k*65 + lane + 32];
        }
        float* orow = out + (size_t)(b*SEQ + q)*HID + h*HD;
        orow[lane]      = o0;
        orow[lane + 32] = o1;
        __syncwarp();
    }
}

// ---------------- launch ------------------------------------------------------
extern "C" void kernel_launch(void* const* d_in, const int* in_sizes, int n_in,
                              void* d_out, int out_size){
    const float* hs    = (const float*)d_in[0];
    const float* wq    = (const float*)d_in[1];
    const float* bq    = (const float*)d_in[2];
    const float* wk    = (const float*)d_in[3];
    const float* wv    = (const float*)d_in[4];
    const float* bv    = (const float*)d_in[5];
    const float* table = (const float*)d_in[6];

    float *q, *k, *v, *bias;
    cudaGetSymbolAddress((void**)&q,    g_q);
    cudaGetSymbolAddress((void**)&k,    g_k);
    cudaGetSymbolAddress((void**)&v,    g_v);
    cudaGetSymbolAddress((void**)&bias, g_bias);

    const int kv_smem = 2 * SEQ * 65 * (int)sizeof(float);   // 102,440 B
    cudaFuncSetAttribute(attention, cudaFuncAttributeMaxDynamicSharedMemorySize, kv_smem);

    dim3 gg((MTOT + BM - 1) / BM, HID / BN);   // 99 x 12
    qkv_gemm<<<gg, 256>>>(hs, wq, bq,      q);
    qkv_gemm<<<gg, 256>>>(hs, wk, nullptr, k);
    qkv_gemm<<<gg, 256>>>(hs, wv, bv,      v);

    build_bias<<<(SEQ*SEQ + 255) / 256, 256>>>(table, bias);

    attention<<<BATCH*NHEAD, 256, kv_smem>>>(q, k, v, bias, (float*)d_out);
}

// round 2
// speedup vs baseline: 1.9390x; 1.9390x over previous
#include <cuda_runtime.h>
#include <cstdint>

#define SEQ    197
#define BATCH  64
#define HID    768
#define NHEAD  12
#define HD     64
#define MTOT   (BATCH*SEQ)      // 12608
#define NUMREL 732

// ---------------- scratch (module-static device memory; no runtime alloc) ----
__device__ float g_q[MTOT*HID];
__device__ float g_k[MTOT*HID];
__device__ float g_v[MTOT*HID];
__device__ float g_bias[NHEAD*SEQ*SEQ];

// ---------------- helpers ----------------------------------------------------
__device__ __forceinline__ float f2tf(float f){
    uint32_t u; asm("cvt.rna.tf32.f32 %0, %1;" : "=r"(u) : "f"(f));
    return __uint_as_float(u);
}

__device__ __forceinline__ void mma8(float* d, const uint32_t* a, const uint32_t* b){
    asm volatile("mma.sync.aligned.m16n8k8.row.col.f32.tf32.tf32.f32 "
        "{%0,%1,%2,%3}, {%4,%5,%6,%7}, {%8,%9}, {%0,%1,%2,%3};"
        : "+f"(d[0]), "+f"(d[1]), "+f"(d[2]), "+f"(d[3])
        : "r"(a[0]), "r"(a[1]), "r"(a[2]), "r"(a[3]), "r"(b[0]), "r"(b[1]));
}

// ---------------- QKV projection GEMM (tf32 tensor cores, v2) -----------------
// C[12608,768] = A @ W (+bias). 128x128 block tile, BK=16, warp tile 64x32,
// double-buffered smem + register prefetch of next global tile.
#define BM 128
#define BN 128
#define BK 16

__global__ __launch_bounds__(256,2) void qkv_gemm(const float* __restrict__ A,
                                                  const float* __restrict__ W,
                                                  const float* __restrict__ bias,
                                                  float* __restrict__ C){
    __shared__ float As[2][BM][BK+4];    // [M][K] layout, pad 4 -> conflict-free frags
    __shared__ float Ws[2][BK][BN+8];    // [K][N] layout, pad 8 -> conflict-free frags

    const int bm = blockIdx.x * BM, bn = blockIdx.y * BN;
    const int tid = threadIdx.x, wid = tid >> 5, lane = tid & 31;
    const int wm = (wid & 1) * 64;       // 2 warps tile M (64 each)
    const int wn = (wid >> 1) * 32;      // 4 warps tile N (32 each)
    const int g  = lane >> 2, tg = lane & 3;

    // per-thread staging coords
    const int ar = tid >> 2,        ac = (tid & 3) * 4;        // A: i=0 slice
    const int ar2 = (tid+256) >> 2, ac2 = ((tid+256) & 3) * 4; // A: i=1 slice
    const int wr = tid >> 5,        wc = (tid & 31) * 4;
    const int wr2 = (tid+256) >> 5, wc2 = ((tid+256) & 31) * 4;

    float acc[4][4][4];
    #pragma unroll
    for(int i=0;i<4;i++)
        #pragma unroll
        for(int j=0;j<4;j++)
            #pragma unroll
            for(int r=0;r<4;r++) acc[i][j][r] = 0.f;

    // ---- prologue: stage tile k0=0 ----
    {
        float4 a0 = (bm+ar  < MTOT) ? *(const float4*)(A + (size_t)(bm+ar )*HID + ac ) : make_float4(0,0,0,0);
        float4 a1 = (bm+ar2 < MTOT) ? *(const float4*)(A + (size_t)(bm+ar2)*HID + ac2) : make_float4(0,0,0,0);
        float4 w0 = *(const float4*)(W + (size_t)wr *HID + bn + wc );
        float4 w1 = *(const float4*)(W + (size_t)wr2*HID + bn + wc2);
        As[0][ar ][ac +0]=f2tf(a0.x); As[0][ar ][ac +1]=f2tf(a0.y); As[0][ar ][ac +2]=f2tf(a0.z); As[0][ar ][ac +3]=f2tf(a0.w);
        As[0][ar2][ac2+0]=f2tf(a1.x); As[0][ar2][ac2+1]=f2tf(a1.y); As[0][ar2][ac2+2]=f2tf(a1.z); As[0][ar2][ac2+3]=f2tf(a1.w);
        Ws[0][wr ][wc +0]=f2tf(w0.x); Ws[0][wr ][wc +1]=f2tf(w0.y); Ws[0][wr ][wc +2]=f2tf(w0.z); Ws[0][wr ][wc +3]=f2tf(w0.w);
        Ws[0][wr2][wc2+0]=f2tf(w1.x); Ws[0][wr2][wc2+1]=f2tf(w1.y); Ws[0][wr2][wc2+2]=f2tf(w1.z); Ws[0][wr2][wc2+3]=f2tf(w1.w);
    }
    __syncthreads();

    int buf = 0;
    for(int k0 = 0; k0 < HID; k0 += BK){
        const bool nxt = (k0 + BK) < HID;
        float4 ap0, ap1, wp0, wp1;
        if(nxt){
            const int kn = k0 + BK;
            ap0 = (bm+ar  < MTOT) ? *(const float4*)(A + (size_t)(bm+ar )*HID + kn + ac ) : make_float4(0,0,0,0);
            ap1 = (bm+ar2 < MTOT) ? *(const float4*)(A + (size_t)(bm+ar2)*HID + kn + ac2) : make_float4(0,0,0,0);
            wp0 = *(const float4*)(W + (size_t)(kn+wr )*HID + bn + wc );
            wp1 = *(const float4*)(W + (size_t)(kn+wr2)*HID + bn + wc2);
        }

        #pragma unroll
        for(int kk = 0; kk < BK; kk += 8){
            uint32_t af[4][4], bf[4][2];
            #pragma unroll
            for(int mi=0;mi<4;mi++){
                int r = wm + mi*16 + g;
                af[mi][0] = __float_as_uint(As[buf][r  ][kk+tg  ]);
                af[mi][1] = __float_as_uint(As[buf][r+8][kk+tg  ]);
                af[mi][2] = __float_as_uint(As[buf][r  ][kk+tg+4]);
                af[mi][3] = __float_as_uint(As[buf][r+8][kk+tg+4]);
            }
            #pragma unroll
            for(int ni=0;ni<4;ni++){
                int c = wn + ni*8 + g;
                bf[ni][0] = __float_as_uint(Ws[buf][kk+tg  ][c]);
                bf[ni][1] = __float_as_uint(Ws[buf][kk+tg+4][c]);
            }
            #pragma unroll
            for(int mi=0;mi<4;mi++)
                #pragma unroll
                for(int ni=0;ni<4;ni++)
                    mma8(acc[mi][ni], af[mi], bf[ni]);
        }

        if(nxt){
            const int nb = buf ^ 1;
            As[nb][ar ][ac +0]=f2tf(ap0.x); As[nb][ar ][ac +1]=f2tf(ap0.y); As[nb][ar ][ac +2]=f2tf(ap0.z); As[nb][ar ][ac +3]=f2tf(ap0.w);
            As[nb][ar2][ac2+0]=f2tf(ap1.x); As[nb][ar2][ac2+1]=f2tf(ap1.y); As[nb][ar2][ac2+2]=f2tf(ap1.z); As[nb][ar2][ac2+3]=f2tf(ap1.w);
            Ws[nb][wr ][wc +0]=f2tf(wp0.x); Ws[nb][wr ][wc +1]=f2tf(wp0.y); Ws[nb][wr ][wc +2]=f2tf(wp0.z); Ws[nb][wr ][wc +3]=f2tf(wp0.w);
            Ws[nb][wr2][wc2+0]=f2tf(wp1.x); Ws[nb][wr2][wc2+1]=f2tf(wp1.y); Ws[nb][wr2][wc2+2]=f2tf(wp1.z); Ws[nb][wr2][wc2+3]=f2tf(wp1.w);
            __syncthreads();
            buf = nb;
        }
    }

    // ---- epilogue: bias + store ----
    #pragma unroll
    for(int mi=0;mi<4;mi++){
        #pragma unroll
        for(int ni=0;ni<4;ni++){
            int col = bn + wn + ni*8 + tg*2;
            float b0 = bias ? bias[col]   : 0.f;
            float b1 = bias ? bias[col+1] : 0.f;
            int r0 = bm + wm + mi*16 + g;
            if(r0 < MTOT){
                C[(size_t)r0*HID+col]   = acc[mi][ni][0] + b0;
                C[(size_t)r0*HID+col+1] = acc[mi][ni][1] + b1;
            }
            int r1 = r0 + 8;
            if(r1 < MTOT){
                C[(size_t)r1*HID+col]   = acc[mi][ni][2] + b0;
                C[(size_t)r1*HID+col+1] = acc[mi][ni][3] + b1;
            }
        }
    }
}

// ---------------- relative position bias build --------------------------------
__global__ void build_bias(const float* __restrict__ table, float* __restrict__ bias){
    int qk = blockIdx.x * blockDim.x + threadIdx.x;
    if(qk >= SEQ*SEQ) return;
    int q = qk / SEQ, k = qk % SEQ;
    int idx;
    if(q == 0 && k == 0)      idx = NUMREL - 1;
    else if(q == 0)           idx = NUMREL - 3;
    else if(k == 0)           idx = NUMREL - 2;
    else {
        int i = q - 1, j = k - 1;
        int hi = i / 14, wi = i % 14;
        int hj = j / 14, wj = j % 14;
        idx = (hi - hj + 13) * 27 + (wi - wj + 13);
    }
    #pragma unroll
    for(int h = 0; h < NHEAD; h++)
        bias[h*SEQ*SEQ + qk] = table[idx*NHEAD + h];
}

// ---------------- attention v2: 2-q blocking, one block per (batch, head) ------
#define KPAD 68   // 68 % 4 == 0 -> aligned float4, conflict-free (stride mod 32 = 4)

__global__ __launch_bounds__(256) void attention(const float* __restrict__ Q,
                                                 const float* __restrict__ K,
                                                 const float* __restrict__ V,
                                                 const float* __restrict__ bias,
                                                 float* __restrict__ out){
    extern __shared__ float kvsh[];
    float* Ks = kvsh;               // SEQ*KPAD
    float* Vs = kvsh + SEQ*KPAD;
    __shared__ float Ps[8][2][200];

    const int b = blockIdx.x / NHEAD, h = blockIdx.x % NHEAD;
    const int tid = threadIdx.x, wid = tid >> 5, lane = tid & 31;

    const float* Kb = K + (size_t)(b*SEQ)*HID + h*HD;
    const float* Vb = V + (size_t)(b*SEQ)*HID + h*HD;

    for(int v = tid; v < SEQ*16; v += 256){
        int s = v >> 4, d = (v & 15) * 4;
        *(float4*)(Ks + s*KPAD + d) = *(const float4*)(Kb + (size_t)s*HID + d);
        *(float4*)(Vs + s*KPAD + d) = *(const float4*)(Vb + (size_t)s*HID + d);
    }
    __syncthreads();

    const float* biash = bias + (size_t)h*SEQ*SEQ;
    const float* Qb    = Q + (size_t)(b*SEQ)*HID + h*HD;

    for(int qp = wid; qp < (SEQ+1)/2; qp += 8){
        const int q0 = qp*2, q1 = q0 + 1;
        const bool h1 = (q1 < SEQ);

        // stage both q rows into registers (pre-scaled)
        float4 qv0[16], qv1[16];
        const float* q0r = Qb + (size_t)q0*HID;
        const float* q1r = Qb + (size_t)(h1 ? q1 : q0)*HID;
        #pragma unroll
        for(int t=0;t<16;t++){
            float4 a = *(const float4*)(q0r + 4*t);
            qv0[t] = make_float4(a.x*0.125f, a.y*0.125f, a.z*0.125f, a.w*0.125f);
            float4 c = *(const float4*)(q1r + 4*t);
            qv1[t] = make_float4(c.x*0.125f, c.y*0.125f, c.z*0.125f, c.w*0.125f);
        }

        // scores for both rows: lane handles k = lane + 32*j
        float s0[7], s1[7];
        float m0 = -1e30f, m1 = -1e30f;
        #pragma unroll
        for(int j=0;j<7;j++){
            int k = lane + j*32;
            float d0 = -1e30f, d1 = -1e30f;
            if(k < SEQ){
                const float* kr = Ks + k*KPAD;
                d0 = 0.f; d1 = 0.f;
                #pragma unroll
                for(int t=0;t<16;t++){
                    float4 kv = *(const float4*)(kr + 4*t);
                    d0 += qv0[t].x*kv.x + qv0[t].y*kv.y + qv0[t].z*kv.z + qv0[t].w*kv.w;
                    d1 += qv1[t].x*kv.x + qv1[t].y*kv.y + qv1[t].z*kv.z + qv1[t].w*kv.w;
                }
                d0 += biash[q0*SEQ + k];
                d1 += h1 ? biash[q1*SEQ + k] : 0.f;
            }
            s0[j] = d0; s1[j] = d1;
            m0 = fmaxf(m0, d0); m1 = fmaxf(m1, d1);
        }
        #pragma unroll
        for(int o=16;o;o>>=1){
            m0 = fmaxf(m0, __shfl_xor_sync(0xffffffffu, m0, o));
            m1 = fmaxf(m1, __shfl_xor_sync(0xffffffffu, m1, o));
        }

        float z0 = 0.f, z1 = 0.f;
        #pragma unroll
        for(int j=0;j<7;j++){
            int k = lane + j*32;
            float e0 = __expf(s0[j] - m0);
            float e1 = __expf(s1[j] - m1);
            if(k >= SEQ){ e0 = 0.f; e1 = 0.f; }
            s0[j] = e0; s1[j] = e1;
            z0 += e0; z1 += e1;
        }
        #pragma unroll
        for(int o=16;o;o>>=1){
            z0 += __shfl_xor_sync(0xffffffffu, z0, o);
            z1 += __shfl_xor_sync(0xffffffffu, z1, o);
        }
        const float inv0 = 1.0f / z0, inv1 = 1.0f / z1;

        #pragma unroll
        for(int j=0;j<7;j++){
            int k = lane + j*32;
            if(k < SEQ){
                Ps[wid][0][k] = s0[j] * inv0;
                Ps[wid][1][k] = s1[j] * inv1;
            }
        }
        __syncwarp();

        // PV: lane owns output dims 2*lane, 2*lane+1; V row reused across both q
        float o00=0.f, o01=0.f, o10=0.f, o11=0.f;
        #pragma unroll 2
        for(int k=0;k<SEQ;k++){
            float p0 = Ps[wid][0][k];
            float p1 = Ps[wid][1][k];
            float2 vv = *(const float2*)(Vs + k*KPAD + 2*lane);
            o00 += p0*vv.x; o01 += p0*vv.y;
            o10 += p1*vv.x; o11 += p1*vv.y;
        }
        float* out0 = out + (size_t)(b*SEQ + q0)*HID + h*HD + 2*lane;
        *(float2*)out0 = make_float2(o00, o01);
        if(h1){
            float* out1 = out + (size_t)(b*SEQ + q1)*HID + h*HD + 2*lane;
            *(float2*)out1 = make_float2(o10, o11);
        }
        __syncwarp();
    }
}

// ---------------- launch ------------------------------------------------------
extern "C" void kernel_launch(void* const* d_in, const int* in_sizes, int n_in,
                              void* d_out, int out_size){
    const float* hs    = (const float*)d_in[0];
    const float* wq    = (const float*)d_in[1];
    const float* bq    = (const float*)d_in[2];
    const float* wk    = (const float*)d_in[3];
    const float* wv    = (const float*)d_in[4];
    const float* bv    = (const float*)d_in[5];
    const float* table = (const float*)d_in[6];

    float *q, *k, *v, *bias;
    cudaGetSymbolAddress((void**)&q,    g_q);
    cudaGetSymbolAddress((void**)&k,    g_k);
    cudaGetSymbolAddress((void**)&v,    g_v);
    cudaGetSymbolAddress((void**)&bias, g_bias);

    const int kv_smem = 2 * SEQ * KPAD * (int)sizeof(float);   // 107,168 B
    cudaFuncSetAttribute(attention, cudaFuncAttributeMaxDynamicSharedMemorySize, kv_smem);

    build_bias<<<(SEQ*SEQ + 255) / 256, 256>>>(table, bias);

    dim3 gg((MTOT + BM - 1) / BM, HID / BN);   // 99 x 6
    qkv_gemm<<<gg, 256>>>(hs, wq, bq,      q);
    qkv_gemm<<<gg, 256>>>(hs, wk, nullptr, k);
    qkv_gemm<<<gg, 256>>>(hs, wv, bv,      v);

    attention<<<BATCH*NHEAD, 256, kv_smem>>>(q, k, v, bias, (float*)d_out);
}

// round 6
// speedup vs baseline: 1.9504x; 1.0059x over previous
#include <cuda_runtime.h>
#include <cstdint>

#define SEQ    197
#define BATCH  64
#define HID    768
#define NHEAD  12
#define HD     64
#define MTOT   (BATCH*SEQ)      // 12608
#define NUMREL 732

// ---------------- scratch (module-static device memory; no runtime alloc) ----
__device__ float g_q[MTOT*HID];
__device__ float g_k[MTOT*HID];
__device__ float g_v[MTOT*HID];
__device__ float g_bias[NHEAD*SEQ*SEQ];

// ---------------- helpers ----------------------------------------------------
__device__ __forceinline__ float f2tf(float f){
    uint32_t u; asm("cvt.rna.tf32.f32 %0, %1;" : "=r"(u) : "f"(f));
    return __uint_as_float(u);
}

__device__ __forceinline__ void mma8(float* d, const uint32_t* a, const uint32_t* b){
    asm volatile("mma.sync.aligned.m16n8k8.row.col.f32.tf32.tf32.f32 "
        "{%0,%1,%2,%3}, {%4,%5,%6,%7}, {%8,%9}, {%0,%1,%2,%3};"
        : "+f"(d[0]), "+f"(d[1]), "+f"(d[2]), "+f"(d[3])
        : "r"(a[0]), "r"(a[1]), "r"(a[2]), "r"(a[3]), "r"(b[0]), "r"(b[1]));
}

// ---------------- QKV projection GEMM (tf32 tensor cores, v2 — unchanged) ----
#define BM 128
#define BN 128
#define BK 16

__global__ __launch_bounds__(256,2) void qkv_gemm(const float* __restrict__ A,
                                                  const float* __restrict__ W,
                                                  const float* __restrict__ bias,
                                                  float* __restrict__ C){
    __shared__ float As[2][BM][BK+4];
    __shared__ float Ws[2][BK][BN+8];

    const int bm = blockIdx.x * BM, bn = blockIdx.y * BN;
    const int tid = threadIdx.x, wid = tid >> 5, lane = tid & 31;
    const int wm = (wid & 1) * 64;
    const int wn = (wid >> 1) * 32;
    const int g  = lane >> 2, tg = lane & 3;

    const int ar = tid >> 2,        ac = (tid & 3) * 4;
    const int ar2 = (tid+256) >> 2, ac2 = ((tid+256) & 3) * 4;
    const int wr = tid >> 5,        wc = (tid & 31) * 4;
    const int wr2 = (tid+256) >> 5, wc2 = ((tid+256) & 31) * 4;

    float acc[4][4][4];
    #pragma unroll
    for(int i=0;i<4;i++)
        #pragma unroll
        for(int j=0;j<4;j++)
            #pragma unroll
            for(int r=0;r<4;r++) acc[i][j][r] = 0.f;

    {
        float4 a0 = (bm+ar  < MTOT) ? *(const float4*)(A + (size_t)(bm+ar )*HID + ac ) : make_float4(0,0,0,0);
        float4 a1 = (bm+ar2 < MTOT) ? *(const float4*)(A + (size_t)(bm+ar2)*HID + ac2) : make_float4(0,0,0,0);
        float4 w0 = *(const float4*)(W + (size_t)wr *HID + bn + wc );
        float4 w1 = *(const float4*)(W + (size_t)wr2*HID + bn + wc2);
        As[0][ar ][ac +0]=f2tf(a0.x); As[0][ar ][ac +1]=f2tf(a0.y); As[0][ar ][ac +2]=f2tf(a0.z); As[0][ar ][ac +3]=f2tf(a0.w);
        As[0][ar2][ac2+0]=f2tf(a1.x); As[0][ar2][ac2+1]=f2tf(a1.y); As[0][ar2][ac2+2]=f2tf(a1.z); As[0][ar2][ac2+3]=f2tf(a1.w);
        Ws[0][wr ][wc +0]=f2tf(w0.x); Ws[0][wr ][wc +1]=f2tf(w0.y); Ws[0][wr ][wc +2]=f2tf(w0.z); Ws[0][wr ][wc +3]=f2tf(w0.w);
        Ws[0][wr2][wc2+0]=f2tf(w1.x); Ws[0][wr2][wc2+1]=f2tf(w1.y); Ws[0][wr2][wc2+2]=f2tf(w1.z); Ws[0][wr2][wc2+3]=f2tf(w1.w);
    }
    __syncthreads();

    int buf = 0;
    for(int k0 = 0; k0 < HID; k0 += BK){
        const bool nxt = (k0 + BK) < HID;
        float4 ap0, ap1, wp0, wp1;
        if(nxt){
            const int kn = k0 + BK;
            ap0 = (bm+ar  < MTOT) ? *(const float4*)(A + (size_t)(bm+ar )*HID + kn + ac ) : make_float4(0,0,0,0);
            ap1 = (bm+ar2 < MTOT) ? *(const float4*)(A + (size_t)(bm+ar2)*HID + kn + ac2) : make_float4(0,0,0,0);
            wp0 = *(const float4*)(W + (size_t)(kn+wr )*HID + bn + wc );
            wp1 = *(const float4*)(W + (size_t)(kn+wr2)*HID + bn + wc2);
        }

        #pragma unroll
        for(int kk = 0; kk < BK; kk += 8){
            uint32_t af[4][4], bf[4][2];
            #pragma unroll
            for(int mi=0;mi<4;mi++){
                int r = wm + mi*16 + g;
                af[mi][0] = __float_as_uint(As[buf][r  ][kk+tg  ]);
                af[mi][1] = __float_as_uint(As[buf][r+8][kk+tg  ]);
                af[mi][2] = __float_as_uint(As[buf][r  ][kk+tg+4]);
                af[mi][3] = __float_as_uint(As[buf][r+8][kk+tg+4]);
            }
            #pragma unroll
            for(int ni=0;ni<4;ni++){
                int c = wn + ni*8 + g;
                bf[ni][0] = __float_as_uint(Ws[buf][kk+tg  ][c]);
                bf[ni][1] = __float_as_uint(Ws[buf][kk+tg+4][c]);
            }
            #pragma unroll
            for(int mi=0;mi<4;mi++)
                #pragma unroll
                for(int ni=0;ni<4;ni++)
                    mma8(acc[mi][ni], af[mi], bf[ni]);
        }

        if(nxt){
            const int nb = buf ^ 1;
            As[nb][ar ][ac +0]=f2tf(ap0.x); As[nb][ar ][ac +1]=f2tf(ap0.y); As[nb][ar ][ac +2]=f2tf(ap0.z); As[nb][ar ][ac +3]=f2tf(ap0.w);
            As[nb][ar2][ac2+0]=f2tf(ap1.x); As[nb][ar2][ac2+1]=f2tf(ap1.y); As[nb][ar2][ac2+2]=f2tf(ap1.z); As[nb][ar2][ac2+3]=f2tf(ap1.w);
            Ws[nb][wr ][wc +0]=f2tf(wp0.x); Ws[nb][wr ][wc +1]=f2tf(wp0.y); Ws[nb][wr ][wc +2]=f2tf(wp0.z); Ws[nb][wr ][wc +3]=f2tf(wp0.w);
            Ws[nb][wr2][wc2+0]=f2tf(wp1.x); Ws[nb][wr2][wc2+1]=f2tf(wp1.y); Ws[nb][wr2][wc2+2]=f2tf(wp1.z); Ws[nb][wr2][wc2+3]=f2tf(wp1.w);
            __syncthreads();
            buf = nb;
        }
    }

    #pragma unroll
    for(int mi=0;mi<4;mi++){
        #pragma unroll
        for(int ni=0;ni<4;ni++){
            int col = bn + wn + ni*8 + tg*2;
            float b0 = bias ? bias[col]   : 0.f;
            float b1 = bias ? bias[col+1] : 0.f;
            int r0 = bm + wm + mi*16 + g;
            if(r0 < MTOT){
                C[(size_t)r0*HID+col]   = acc[mi][ni][0] + b0;
                C[(size_t)r0*HID+col+1] = acc[mi][ni][1] + b1;
            }
            int r1 = r0 + 8;
            if(r1 < MTOT){
                C[(size_t)r1*HID+col]   = acc[mi][ni][2] + b0;
                C[(size_t)r1*HID+col+1] = acc[mi][ni][3] + b1;
            }
        }
    }
}

// ---------------- relative position bias build --------------------------------
__global__ void build_bias(const float* __restrict__ table, float* __restrict__ bias){
    int qk = blockIdx.x * blockDim.x + threadIdx.x;
    if(qk >= SEQ*SEQ) return;
    int q = qk / SEQ, k = qk % SEQ;
    int idx;
    if(q == 0 && k == 0)      idx = NUMREL - 1;
    else if(q == 0)           idx = NUMREL - 3;
    else if(k == 0)           idx = NUMREL - 2;
    else {
        int i = q - 1, j = k - 1;
        int hi = i / 14, wi = i % 14;
        int hj = j / 14, wj = j % 14;
        idx = (hi - hj + 13) * 27 + (wi - wj + 13);
    }
    #pragma unroll
    for(int h = 0; h < NHEAD; h++)
        bias[h*SEQ*SEQ + qk] = table[idx*NHEAD + h];
}

// ---------------- attention v3: XOR-swizzled K/V smem, conflict-free ----------
// Row s, float4-chunk t stored at  s*64 + 4*(t ^ (s&7)).
//  - score loop (row varies with lane): conflict-free LDS.128
//  - PV loop  (row fixed, dim varies): conflict-free LDS.64
__global__ __launch_bounds__(256) void attention(const float* __restrict__ Q,
                                                 const float* __restrict__ K,
                                                 const float* __restrict__ V,
                                                 const float* __restrict__ bias,
                                                 float* __restrict__ out){
    extern __shared__ float kvsh[];
    float* Ks = kvsh;               // SEQ*64 swizzled
    float* Vs = kvsh + SEQ*HD;
    __shared__ float Ps[8][2][200];

    const int b = blockIdx.x / NHEAD, h = blockIdx.x % NHEAD;
    const int tid = threadIdx.x, wid = tid >> 5, lane = tid & 31;

    const float* Kb = K + (size_t)(b*SEQ)*HID + h*HD;
    const float* Vb = V + (size_t)(b*SEQ)*HID + h*HD;

    for(int v = tid; v < SEQ*16; v += 256){
        int s = v >> 4, t = v & 15;
        int sw = s*HD + 4*(t ^ (s & 7));
        *(float4*)(Ks + sw) = *(const float4*)(Kb + (size_t)s*HID + 4*t);
        *(float4*)(Vs + sw) = *(const float4*)(Vb + (size_t)s*HID + 4*t);
    }
    __syncthreads();

    const float* biash = bias + (size_t)h*SEQ*SEQ;
    const float* Qb    = Q + (size_t)(b*SEQ)*HID + h*HD;

    for(int qp = wid; qp < (SEQ+1)/2; qp += 8){
        const int q0 = qp*2, q1 = q0 + 1;
        const bool h1 = (q1 < SEQ);

        float4 qv0[16], qv1[16];
        const float* q0r = Qb + (size_t)q0*HID;
        const float* q1r = Qb + (size_t)(h1 ? q1 : q0)*HID;
        #pragma unroll
        for(int t=0;t<16;t++){
            float4 a = *(const float4*)(q0r + 4*t);
            qv0[t] = make_float4(a.x*0.125f, a.y*0.125f, a.z*0.125f, a.w*0.125f);
            float4 c = *(const float4*)(q1r + 4*t);
            qv1[t] = make_float4(c.x*0.125f, c.y*0.125f, c.z*0.125f, c.w*0.125f);
        }

        float s0[7], s1[7];
        float m0 = -1e30f, m1 = -1e30f;
        #pragma unroll
        for(int j=0;j<7;j++){
            int k = lane + j*32;
            float d0 = -1e30f, d1 = -1e30f;
            if(k < SEQ){
                const float* kr = Ks + k*HD;
                const int kx = k & 7;
                d0 = 0.f; d1 = 0.f;
                #pragma unroll
                for(int t=0;t<16;t++){
                    float4 kv = *(const float4*)(kr + 4*(t ^ kx));
                    d0 += qv0[t].x*kv.x + qv0[t].y*kv.y + qv0[t].z*kv.z + qv0[t].w*kv.w;
                    d1 += qv1[t].x*kv.x + qv1[t].y*kv.y + qv1[t].z*kv.z + qv1[t].w*kv.w;
                }
                d0 += biash[q0*SEQ + k];
                d1 += h1 ? biash[q1*SEQ + k] : 0.f;
            }
            s0[j] = d0; s1[j] = d1;
            m0 = fmaxf(m0, d0); m1 = fmaxf(m1, d1);
        }
        #pragma unroll
        for(int o=16;o;o>>=1){
            m0 = fmaxf(m0, __shfl_xor_sync(0xffffffffu, m0, o));
            m1 = fmaxf(m1, __shfl_xor_sync(0xffffffffu, m1, o));
        }

        float z0 = 0.f, z1 = 0.f;
        #pragma unroll
        for(int j=0;j<7;j++){
            int k = lane + j*32;
            float e0 = __expf(s0[j] - m0);
            float e1 = __expf(s1[j] - m1);
            if(k >= SEQ){ e0 = 0.f; e1 = 0.f; }
            s0[j] = e0; s1[j] = e1;
            z0 += e0; z1 += e1;
        }
        #pragma unroll
        for(int o=16;o;o>>=1){
            z0 += __shfl_xor_sync(0xffffffffu, z0, o);
            z1 += __shfl_xor_sync(0xffffffffu, z1, o);
        }
        const float inv0 = 1.0f / z0, inv1 = 1.0f / z1;

        #pragma unroll
        for(int j=0;j<7;j++){
            int k = lane + j*32;
            if(k < SEQ){
                Ps[wid][0][k] = s0[j] * inv0;
                Ps[wid][1][k] = s1[j] * inv1;
            }
        }
        __syncwarp();

        // PV: lane owns dims 2*lane, 2*lane+1 (swizzle-aware float2 loads)
        const int tc   = lane >> 1;
        const int sub  = (lane & 1) * 2;
        float o00=0.f, o01=0.f, o10=0.f, o11=0.f;
        #pragma unroll 4
        for(int k=0;k<SEQ;k++){
            float p0 = Ps[wid][0][k];
            float p1 = Ps[wid][1][k];
            float2 vv = *(const float2*)(Vs + k*HD + 4*(tc ^ (k & 7)) + sub);
            o00 += p0*vv.x; o01 += p0*vv.y;
            o10 += p1*vv.x; o11 += p1*vv.y;
        }
        float* out0 = out + (size_t)(b*SEQ + q0)*HID + h*HD + 2*lane;
        *(float2*)out0 = make_float2(o00, o01);
        if(h1){
            float* out1 = out + (size_t)(b*SEQ + q1)*HID + h*HD + 2*lane;
            *(float2*)out1 = make_float2(o10, o11);
        }
        __syncwarp();
    }
}

// ---------------- launch ------------------------------------------------------
extern "C" void kernel_launch(void* const* d_in, const int* in_sizes, int n_in,
                              void* d_out, int out_size){
    const float* hs    = (const float*)d_in[0];
    const float* wq    = (const float*)d_in[1];
    const float* bq    = (const float*)d_in[2];
    const float* wk    = (const float*)d_in[3];
    const float* wv    = (const float*)d_in[4];
    const float* bv    = (const float*)d_in[5];
    const float* table = (const float*)d_in[6];

    float *q, *k, *v, *bias;
    cudaGetSymbolAddress((void**)&q,    g_q);
    cudaGetSymbolAddress((void**)&k,    g_k);
    cudaGetSymbolAddress((void**)&v,    g_v);
    cudaGetSymbolAddress((void**)&bias, g_bias);

    const int kv_smem = 2 * SEQ * HD * (int)sizeof(float);   // 100,864 B
    cudaFuncSetAttribute(attention, cudaFuncAttributeMaxDynamicSharedMemorySize, kv_smem);

    build_bias<<<(SEQ*SEQ + 255) / 256, 256>>>(table, bias);

    dim3 gg((MTOT + BM - 1) / BM, HID / BN);
    qkv_gemm<<<gg, 256>>>(hs, wq, bq,      q);
    qkv_gemm<<<gg, 256>>>(hs, wk, nullptr, k);
    qkv_gemm<<<gg, 256>>>(hs, wv, bv,      v);

    attention<<<BATCH*NHEAD, 256, kv_smem>>>(q, k, v, bias, (float*)d_out);
}

// round 7
// speedup vs baseline: 3.2346x; 1.6584x over previous
#include <cuda_runtime.h>
#include <cstdint>

#define SEQ    197
#define BATCH  64
#define HID    768
#define NHEAD  12
#define HD     64
#define MTOT   (BATCH*SEQ)      // 12608
#define NUMREL 732
#define NK     200              // padded seq (25 x 8)
#define SP     204              // Vt / Ps pitch (conflict-free: 204 mod 32 = 12)
#define BPITCH 200              // bias row pitch (even -> aligned float2)

// ---------------- scratch -----------------------------------------------------
__device__ float g_q[MTOT*HID];
__device__ float g_k[MTOT*HID];
__device__ float g_v[MTOT*HID];
__device__ float g_bias[NHEAD*SEQ*BPITCH];

// ---------------- helpers ----------------------------------------------------
__device__ __forceinline__ float f2tf(float f){
    uint32_t u; asm("cvt.rna.tf32.f32 %0, %1;" : "=r"(u) : "f"(f));
    return __uint_as_float(u);
}
__device__ __forceinline__ uint32_t f2tfu(float f){
    uint32_t u; asm("cvt.rna.tf32.f32 %0, %1;" : "=r"(u) : "f"(f));
    return u;
}
__device__ __forceinline__ void mma8(float* d, const uint32_t* a, const uint32_t* b){
    asm volatile("mma.sync.aligned.m16n8k8.row.col.f32.tf32.tf32.f32 "
        "{%0,%1,%2,%3}, {%4,%5,%6,%7}, {%8,%9}, {%0,%1,%2,%3};"
        : "+f"(d[0]), "+f"(d[1]), "+f"(d[2]), "+f"(d[3])
        : "r"(a[0]), "r"(a[1]), "r"(a[2]), "r"(a[3]), "r"(b[0]), "r"(b[1]));
}

// ---------------- QKV projection GEMM (unchanged, verified) -------------------
#define BM 128
#define BN 128
#define BK 16

__global__ __launch_bounds__(256,2) void qkv_gemm(const float* __restrict__ A,
                                                  const float* __restrict__ W,
                                                  const float* __restrict__ bias,
                                                  float* __restrict__ C){
    __shared__ float As[2][BM][BK+4];
    __shared__ float Ws[2][BK][BN+8];

    const int bm = blockIdx.x * BM, bn = blockIdx.y * BN;
    const int tid = threadIdx.x, wid = tid >> 5, lane = tid & 31;
    const int wm = (wid & 1) * 64;
    const int wn = (wid >> 1) * 32;
    const int g  = lane >> 2, tg = lane & 3;

    const int ar = tid >> 2,        ac = (tid & 3) * 4;
    const int ar2 = (tid+256) >> 2, ac2 = ((tid+256) & 3) * 4;
    const int wr = tid >> 5,        wc = (tid & 31) * 4;
    const int wr2 = (tid+256) >> 5, wc2 = ((tid+256) & 31) * 4;

    float acc[4][4][4];
    #pragma unroll
    for(int i=0;i<4;i++)
        #pragma unroll
        for(int j=0;j<4;j++)
            #pragma unroll
            for(int r=0;r<4;r++) acc[i][j][r] = 0.f;

    {
        float4 a0 = (bm+ar  < MTOT) ? *(const float4*)(A + (size_t)(bm+ar )*HID + ac ) : make_float4(0,0,0,0);
        float4 a1 = (bm+ar2 < MTOT) ? *(const float4*)(A + (size_t)(bm+ar2)*HID + ac2) : make_float4(0,0,0,0);
        float4 w0 = *(const float4*)(W + (size_t)wr *HID + bn + wc );
        float4 w1 = *(const float4*)(W + (size_t)wr2*HID + bn + wc2);
        As[0][ar ][ac +0]=f2tf(a0.x); As[0][ar ][ac +1]=f2tf(a0.y); As[0][ar ][ac +2]=f2tf(a0.z); As[0][ar ][ac +3]=f2tf(a0.w);
        As[0][ar2][ac2+0]=f2tf(a1.x); As[0][ar2][ac2+1]=f2tf(a1.y); As[0][ar2][ac2+2]=f2tf(a1.z); As[0][ar2][ac2+3]=f2tf(a1.w);
        Ws[0][wr ][wc +0]=f2tf(w0.x); Ws[0][wr ][wc +1]=f2tf(w0.y); Ws[0][wr ][wc +2]=f2tf(w0.z); Ws[0][wr ][wc +3]=f2tf(w0.w);
        Ws[0][wr2][wc2+0]=f2tf(w1.x); Ws[0][wr2][wc2+1]=f2tf(w1.y); Ws[0][wr2][wc2+2]=f2tf(w1.z); Ws[0][wr2][wc2+3]=f2tf(w1.w);
    }
    __syncthreads();

    int buf = 0;
    for(int k0 = 0; k0 < HID; k0 += BK){
        const bool nxt = (k0 + BK) < HID;
        float4 ap0, ap1, wp0, wp1;
        if(nxt){
            const int kn = k0 + BK;
            ap0 = (bm+ar  < MTOT) ? *(const float4*)(A + (size_t)(bm+ar )*HID + kn + ac ) : make_float4(0,0,0,0);
            ap1 = (bm+ar2 < MTOT) ? *(const float4*)(A + (size_t)(bm+ar2)*HID + kn + ac2) : make_float4(0,0,0,0);
            wp0 = *(const float4*)(W + (size_t)(kn+wr )*HID + bn + wc );
            wp1 = *(const float4*)(W + (size_t)(kn+wr2)*HID + bn + wc2);
        }

        #pragma unroll
        for(int kk = 0; kk < BK; kk += 8){
            uint32_t af[4][4], bf[4][2];
            #pragma unroll
            for(int mi=0;mi<4;mi++){
                int r = wm + mi*16 + g;
                af[mi][0] = __float_as_uint(As[buf][r  ][kk+tg  ]);
                af[mi][1] = __float_as_uint(As[buf][r+8][kk+tg  ]);
                af[mi][2] = __float_as_uint(As[buf][r  ][kk+tg+4]);
                af[mi][3] = __float_as_uint(As[buf][r+8][kk+tg+4]);
            }
            #pragma unroll
            for(int ni=0;ni<4;ni++){
                int c = wn + ni*8 + g;
                bf[ni][0] = __float_as_uint(Ws[buf][kk+tg  ][c]);
                bf[ni][1] = __float_as_uint(Ws[buf][kk+tg+4][c]);
            }
            #pragma unroll
            for(int mi=0;mi<4;mi++)
                #pragma unroll
                for(int ni=0;ni<4;ni++)
                    mma8(acc[mi][ni], af[mi], bf[ni]);
        }

        if(nxt){
            const int nb = buf ^ 1;
            As[nb][ar ][ac +0]=f2tf(ap0.x); As[nb][ar ][ac +1]=f2tf(ap0.y); As[nb][ar ][ac +2]=f2tf(ap0.z); As[nb][ar ][ac +3]=f2tf(ap0.w);
            As[nb][ar2][ac2+0]=f2tf(ap1.x); As[nb][ar2][ac2+1]=f2tf(ap1.y); As[nb][ar2][ac2+2]=f2tf(ap1.z); As[nb][ar2][ac2+3]=f2tf(ap1.w);
            Ws[nb][wr ][wc +0]=f2tf(wp0.x); Ws[nb][wr ][wc +1]=f2tf(wp0.y); Ws[nb][wr ][wc +2]=f2tf(wp0.z); Ws[nb][wr ][wc +3]=f2tf(wp0.w);
            Ws[nb][wr2][wc2+0]=f2tf(wp1.x); Ws[nb][wr2][wc2+1]=f2tf(wp1.y); Ws[nb][wr2][wc2+2]=f2tf(wp1.z); Ws[nb][wr2][wc2+3]=f2tf(wp1.w);
            __syncthreads();
            buf = nb;
        }
    }

    #pragma unroll
    for(int mi=0;mi<4;mi++){
        #pragma unroll
        for(int ni=0;ni<4;ni++){
            int col = bn + wn + ni*8 + tg*2;
            float b0 = bias ? bias[col]   : 0.f;
            float b1 = bias ? bias[col+1] : 0.f;
            int r0 = bm + wm + mi*16 + g;
            if(r0 < MTOT){
                C[(size_t)r0*HID+col]   = acc[mi][ni][0] + b0;
                C[(size_t)r0*HID+col+1] = acc[mi][ni][1] + b1;
            }
            int r1 = r0 + 8;
            if(r1 < MTOT){
                C[(size_t)r1*HID+col]   = acc[mi][ni][2] + b0;
                C[(size_t)r1*HID+col+1] = acc[mi][ni][3] + b1;
            }
        }
    }
}

// ---------------- relative position bias (pitch 200) --------------------------
__global__ void build_bias(const float* __restrict__ table, float* __restrict__ bias){
    int qk = blockIdx.x * blockDim.x + threadIdx.x;
    if(qk >= SEQ*SEQ) return;
    int q = qk / SEQ, k = qk % SEQ;
    int idx;
    if(q == 0 && k == 0)      idx = NUMREL - 1;
    else if(q == 0)           idx = NUMREL - 3;
    else if(k == 0)           idx = NUMREL - 2;
    else {
        int i = q - 1, j = k - 1;
        int hi = i / 14, wi = i % 14;
        int hj = j / 14, wj = j % 14;
        idx = (hi - hj + 13) * 27 + (wi - wj + 13);
    }
    #pragma unroll
    for(int h = 0; h < NHEAD; h++)
        bias[(size_t)h*SEQ*BPITCH + q*BPITCH + k] = table[idx*NHEAD + h];
}

// ---------------- attention v4: tensor-core (tf32 mma.m16n8k8) ----------------
// smem: Ks [200 x 64] tf32, XOR-swizzled rows (chunk t at 4*(t^(s&7)))
//       Vt [64 x 204] tf32, transposed (dim-major)
//       Ps [8 warps][16 x 204] tf32 probabilities
__global__ __launch_bounds__(256,1) void attention(const float* __restrict__ Q,
                                                   const float* __restrict__ K,
                                                   const float* __restrict__ V,
                                                   const float* __restrict__ bias,
                                                   float* __restrict__ out){
    extern __shared__ float sm[];
    float* Ks = sm;                       // 200*64   = 12800
    float* Vt = sm + NK*HD;               // 64*204   = 13056
    float* Ps = Vt + HD*SP;               // 8*16*204 = 26112

    const int b = blockIdx.x / NHEAD, h = blockIdx.x % NHEAD;
    const int tid = threadIdx.x, wid = tid >> 5, lane = tid & 31;
    const int g = lane >> 2, tg = lane & 3;

    const float* Kb = K + (size_t)(b*SEQ)*HID + h*HD;
    const float* Vb = V + (size_t)(b*SEQ)*HID + h*HD;
    const float* Qb = Q + (size_t)(b*SEQ)*HID + h*HD;

    // ---- stage K (swizzled, tf32) ----
    for(int v = tid; v < NK*16; v += 256){
        int s = v >> 4, t = v & 15;
        float4 kk = make_float4(0,0,0,0);
        if(s < SEQ) kk = *(const float4*)(Kb + (size_t)s*HID + 4*t);
        float* d = Ks + s*HD + 4*(t ^ (s & 7));
        d[0]=f2tf(kk.x); d[1]=f2tf(kk.y); d[2]=f2tf(kk.z); d[3]=f2tf(kk.w);
    }
    // ---- stage V transposed (tf32) ----
    for(int v = tid; v < NK*HD; v += 256){
        int s = v >> 6, d = v & 63;
        float val = (s < SEQ) ? Vb[(size_t)s*HID + d] : 0.f;
        Vt[d*SP + s] = f2tf(val);
    }
    __syncthreads();

    const float* bh = bias + (size_t)h*SEQ*BPITCH;
    float* Pw = Ps + wid*16*SP;

    for(int tile = wid; tile < 13; tile += 8){
        const int q0 = tile*16;
        const int row0 = q0 + g, row1 = q0 + 8 + g;
        const int r0c = row0 < SEQ ? row0 : SEQ-1;
        const int r1c = row1 < SEQ ? row1 : SEQ-1;

        // ---- Q fragments (pre-scaled, tf32) ----
        uint32_t aq[8][4];
        {
            const float* Q0 = Qb + (size_t)r0c*HID;
            const float* Q1 = Qb + (size_t)r1c*HID;
            #pragma unroll
            for(int ks=0; ks<8; ks++){
                aq[ks][0] = f2tfu(Q0[8*ks+tg  ] * 0.125f);
                aq[ks][1] = f2tfu(Q1[8*ks+tg  ] * 0.125f);
                aq[ks][2] = f2tfu(Q0[8*ks+tg+4] * 0.125f);
                aq[ks][3] = f2tfu(Q1[8*ks+tg+4] * 0.125f);
            }
        }

        // ---- scores S = Q K^T : 25 n-tiles x 8 k-steps ----
        float s[25][4];
        #pragma unroll
        for(int nt=0;nt<25;nt++){ s[nt][0]=0.f; s[nt][1]=0.f; s[nt][2]=0.f; s[nt][3]=0.f; }

        #pragma unroll
        for(int nt=0; nt<25; nt++){
            const float* kr = Ks + (8*nt + g)*HD;
            #pragma unroll
            for(int ks=0; ks<8; ks++){
                uint32_t bb[2];
                bb[0] = __float_as_uint(kr[4*((2*ks  ) ^ g) + tg]);
                bb[1] = __float_as_uint(kr[4*((2*ks+1) ^ g) + tg]);
                mma8(s[nt], aq[ks], bb);
            }
        }

        // ---- bias add + col mask ----
        const float* b0p = bh + (size_t)r0c*BPITCH;
        const float* b1p = bh + (size_t)r1c*BPITCH;
        #pragma unroll
        for(int nt=0; nt<25; nt++){
            int c = 8*nt + 2*tg;
            float2 bv0 = *(const float2*)(b0p + c);
            float2 bv1 = *(const float2*)(b1p + c);
            s[nt][0] += bv0.x; s[nt][1] += bv0.y;
            s[nt][2] += bv1.x; s[nt][3] += bv1.y;
            if(c   >= SEQ){ s[nt][0] = -1e30f; s[nt][2] = -1e30f; }
            if(c+1 >= SEQ){ s[nt][1] = -1e30f; s[nt][3] = -1e30f; }
        }

        // ---- softmax (rows row0, row1) ----
        float m0 = -1e30f, m1 = -1e30f;
        #pragma unroll
        for(int nt=0; nt<25; nt++){
            m0 = fmaxf(m0, fmaxf(s[nt][0], s[nt][1]));
            m1 = fmaxf(m1, fmaxf(s[nt][2], s[nt][3]));
        }
        #pragma unroll
        for(int o=1;o<4;o<<=1){
            m0 = fmaxf(m0, __shfl_xor_sync(0xffffffffu, m0, o));
            m1 = fmaxf(m1, __shfl_xor_sync(0xffffffffu, m1, o));
        }
        float z0 = 0.f, z1 = 0.f;
        #pragma unroll
        for(int nt=0; nt<25; nt++){
            s[nt][0] = __expf(s[nt][0] - m0);
            s[nt][1] = __expf(s[nt][1] - m0);
            s[nt][2] = __expf(s[nt][2] - m1);
            s[nt][3] = __expf(s[nt][3] - m1);
            z0 += s[nt][0] + s[nt][1];
            z1 += s[nt][2] + s[nt][3];
        }
        #pragma unroll
        for(int o=1;o<4;o<<=1){
            z0 += __shfl_xor_sync(0xffffffffu, z0, o);
            z1 += __shfl_xor_sync(0xffffffffu, z1, o);
        }
        const float inv0 = 1.0f / z0, inv1 = 1.0f / z1;

        // ---- P -> smem (tf32) ----
        #pragma unroll
        for(int nt=0; nt<25; nt++){
            int c = 8*nt + 2*tg;
            float2 p0 = make_float2(f2tf(s[nt][0]*inv0), f2tf(s[nt][1]*inv0));
            float2 p1 = make_float2(f2tf(s[nt][2]*inv1), f2tf(s[nt][3]*inv1));
            *(float2*)(Pw + g*SP + c)     = p0;
            *(float2*)(Pw + (g+8)*SP + c) = p1;
        }
        __syncwarp();

        // ---- O = P V : 25 k-steps x 8 n-tiles ----
        float o[8][4];
        #pragma unroll
        for(int nt=0;nt<8;nt++){ o[nt][0]=0.f; o[nt][1]=0.f; o[nt][2]=0.f; o[nt][3]=0.f; }

        #pragma unroll
        for(int ks=0; ks<25; ks++){
            uint32_t a[4];
            a[0] = __float_as_uint(Pw[g*SP     + 8*ks + tg    ]);
            a[1] = __float_as_uint(Pw[(g+8)*SP + 8*ks + tg    ]);
            a[2] = __float_as_uint(Pw[g*SP     + 8*ks + tg + 4]);
            a[3] = __float_as_uint(Pw[(g+8)*SP + 8*ks + tg + 4]);
            #pragma unroll
            for(int nt=0; nt<8; nt++){
                const float* vr = Vt + (8*nt + g)*SP + 8*ks;
                uint32_t bb[2];
                bb[0] = __float_as_uint(vr[tg    ]);
                bb[1] = __float_as_uint(vr[tg + 4]);
                mma8(o[nt], a, bb);
            }
        }

        // ---- store output ----
        #pragma unroll
        for(int nt=0; nt<8; nt++){
            int c = h*HD + 8*nt + 2*tg;
            if(row0 < SEQ)
                *(float2*)(out + (size_t)(b*SEQ + row0)*HID + c) = make_float2(o[nt][0], o[nt][1]);
            if(row1 < SEQ)
                *(float2*)(out + (size_t)(b*SEQ + row1)*HID + c) = make_float2(o[nt][2], o[nt][3]);
        }
        __syncwarp();
    }
}

// ---------------- launch ------------------------------------------------------
extern "C" void kernel_launch(void* const* d_in, const int* in_sizes, int n_in,
                              void* d_out, int out_size){
    const float* hs    = (const float*)d_in[0];
    const float* wq    = (const float*)d_in[1];
    const float* bq    = (const float*)d_in[2];
    const float* wk    = (const float*)d_in[3];
    const float* wv    = (const float*)d_in[4];
    const float* bv    = (const float*)d_in[5];
    const float* table = (const float*)d_in[6];

    float *q, *k, *v, *bias;
    cudaGetSymbolAddress((void**)&q,    g_q);
    cudaGetSymbolAddress((void**)&k,    g_k);
    cudaGetSymbolAddress((void**)&v,    g_v);
    cudaGetSymbolAddress((void**)&bias, g_bias);

    const int attn_smem = (NK*HD + HD*SP + 8*16*SP) * (int)sizeof(float);  // 207,872 B
    cudaFuncSetAttribute(attention, cudaFuncAttributeMaxDynamicSharedMemorySize, attn_smem);

    build_bias<<<(SEQ*SEQ + 255) / 256, 256>>>(table, bias);

    dim3 gg((MTOT + BM - 1) / BM, HID / BN);
    qkv_gemm<<<gg, 256>>>(hs, wq, bq,      q);
    qkv_gemm<<<gg, 256>>>(hs, wk, nullptr, k);
    qkv_gemm<<<gg, 256>>>(hs, wv, bv,      v);

    attention<<<BATCH*NHEAD, 256, attn_smem>>>(q, k, v, bias, (float*)d_out);
}

// round 11
// speedup vs baseline: 3.4978x; 1.0814x over previous
#include <cuda_runtime.h>
#include <cstdint>

#define SEQ    197
#define BATCH  64
#define HID    768
#define NHEAD  12
#define HD     64
#define MTOT   (BATCH*SEQ)      // 12608
#define NUMREL 732
#define NK     200              // padded seq (25 x 8)
#define SP     204              // Vt / Ps pitch
#define BPITCH 200              // bias row pitch

// ---------------- scratch -----------------------------------------------------
__device__ float g_q[MTOT*HID];
__device__ float g_k[MTOT*HID];
__device__ float g_v[MTOT*HID];
__device__ float g_bias[NHEAD*SEQ*BPITCH];

// ---------------- helpers ----------------------------------------------------
__device__ __forceinline__ float f2tf(float f){
    uint32_t u; asm("cvt.rna.tf32.f32 %0, %1;" : "=r"(u) : "f"(f));
    return __uint_as_float(u);
}
__device__ __forceinline__ uint32_t f2tfu(float f){
    uint32_t u; asm("cvt.rna.tf32.f32 %0, %1;" : "=r"(u) : "f"(f));
    return u;
}
__device__ __forceinline__ void mma8(float* d, const uint32_t* a, const uint32_t* b){
    asm volatile("mma.sync.aligned.m16n8k8.row.col.f32.tf32.tf32.f32 "
        "{%0,%1,%2,%3}, {%4,%5,%6,%7}, {%8,%9}, {%0,%1,%2,%3};"
        : "+f"(d[0]), "+f"(d[1]), "+f"(d[2]), "+f"(d[3])
        : "r"(a[0]), "r"(a[1]), "r"(a[2]), "r"(a[3]), "r"(b[0]), "r"(b[1]));
}
__device__ __forceinline__ void cpa16(uint32_t dst, const void* src){
    asm volatile("cp.async.cg.shared.global [%0], [%1], 16;" :: "r"(dst), "l"(src));
}
__device__ __forceinline__ void cpcommit(){ asm volatile("cp.async.commit_group;"); }
template<int N> __device__ __forceinline__ void cpwait(){
    asm volatile("cp.async.wait_group %0;" :: "n"(N));
}

// ---------------- QKV GEMM v3b: 64x64 warp tiles, cp.async, RNA cvt in regs ---
// C[12608,768] = A @ W (+bias). Block 128x128, 128 threads (2x2 warps of 64x64).
#define BM 128
#define BN 128
#define BK 16
#define APITCH 20
#define WPITCH 136
#define ASLOT (BM*APITCH)   // 2560 floats
#define WSLOT (BK*WPITCH)   // 2176 floats
#define GEMM_SMEM (3*(ASLOT+WSLOT)*4)   // 56,832 B

__global__ __launch_bounds__(128,2) void qkv_gemm(const float* __restrict__ A,
                                                  const float* __restrict__ W,
                                                  const float* __restrict__ bias,
                                                  float* __restrict__ C){
    extern __shared__ float sm[];
    float* Asb = sm;               // 3 slots of [128][20]
    float* Wsb = sm + 3*ASLOT;     // 3 slots of [16][136]

    const int bm = blockIdx.x * BM, bn = blockIdx.y * BN;
    const int tid = threadIdx.x, wid = tid >> 5, lane = tid & 31;
    const int wm = (wid & 1) * 64, wn = (wid >> 1) * 64;
    const int g = lane >> 2, tg = lane & 3;

    const uint32_t sbase = (uint32_t)__cvta_generic_to_shared(sm);

    auto stage = [&](int slot, int kc){
        const int k0 = kc * BK;
        #pragma unroll
        for(int i=0;i<4;i++){
            int v = tid + i*128;
            int r = v >> 2, c = (v & 3) * 4;
            int grow = bm + r; if(grow >= MTOT) grow = MTOT-1;
            cpa16(sbase + (uint32_t)(slot*ASLOT + r*APITCH + c)*4u,
                  A + (size_t)grow*HID + k0 + c);
        }
        #pragma unroll
        for(int i=0;i<4;i++){
            int v = tid + i*128;
            int r = v >> 5, c = (v & 31) * 4;
            cpa16(sbase + (uint32_t)(3*ASLOT + slot*WSLOT + r*WPITCH + c)*4u,
                  W + (size_t)(k0+r)*HID + bn + c);
        }
    };

    float acc[4][8][4] = {};

    stage(0,0); cpcommit();
    stage(1,1); cpcommit();

    const int NC = HID / BK;   // 48
    for(int i=0;i<NC;i++){
        cpwait<1>();
        __syncthreads();
        if(i+2 < NC) stage((i+2)%3, i+2);
        cpcommit();

        const float* Ab = Asb + (i%3)*ASLOT;
        const float* Wb = Wsb + (i%3)*WSLOT;

        #pragma unroll
        for(int kk=0; kk<BK; kk+=8){
            uint32_t af[4][4], bf[8][2];
            #pragma unroll
            for(int mi=0;mi<4;mi++){
                const float* ap = Ab + (wm + mi*16 + g)*APITCH + kk + tg;
                af[mi][0] = f2tfu(ap[0]);
                af[mi][1] = f2tfu(ap[8*APITCH]);
                af[mi][2] = f2tfu(ap[4]);
                af[mi][3] = f2tfu(ap[8*APITCH+4]);
            }
            #pragma unroll
            for(int ni=0;ni<8;ni++){
                const float* wp = Wb + (kk+tg)*WPITCH + wn + ni*8 + g;
                bf[ni][0] = f2tfu(wp[0]);
                bf[ni][1] = f2tfu(wp[4*WPITCH]);
            }
            #pragma unroll
            for(int mi=0;mi<4;mi++)
                #pragma unroll
                for(int ni=0;ni<8;ni++)
                    mma8(acc[mi][ni], af[mi], bf[ni]);
        }
    }

    // ---- epilogue: bias + store ----
    #pragma unroll
    for(int mi=0;mi<4;mi++){
        #pragma unroll
        for(int ni=0;ni<8;ni++){
            int col = bn + wn + ni*8 + tg*2;
            float b0 = bias ? bias[col]   : 0.f;
            float b1 = bias ? bias[col+1] : 0.f;
            int r0 = bm + wm + mi*16 + g;
            if(r0 < MTOT)
                *(float2*)(C + (size_t)r0*HID + col) = make_float2(acc[mi][ni][0]+b0, acc[mi][ni][1]+b1);
            int r1 = r0 + 8;
            if(r1 < MTOT)
                *(float2*)(C + (size_t)r1*HID + col) = make_float2(acc[mi][ni][2]+b0, acc[mi][ni][3]+b1);
        }
    }
}

// ---------------- relative position bias (pitch 200) --------------------------
__global__ void build_bias(const float* __restrict__ table, float* __restrict__ bias){
    int qk = blockIdx.x * blockDim.x + threadIdx.x;
    if(qk >= SEQ*SEQ) return;
    int q = qk / SEQ, k = qk % SEQ;
    int idx;
    if(q == 0 && k == 0)      idx = NUMREL - 1;
    else if(q == 0)           idx = NUMREL - 3;
    else if(k == 0)           idx = NUMREL - 2;
    else {
        int i = q - 1, j = k - 1;
        int hi = i / 14, wi = i % 14;
        int hj = j / 14, wj = j % 14;
        idx = (hi - hj + 13) * 27 + (wi - wj + 13);
    }
    #pragma unroll
    for(int h = 0; h < NHEAD; h++)
        bias[(size_t)h*SEQ*BPITCH + q*BPITCH + k] = table[idx*NHEAD + h];
}

// ---------------- attention v4: tensor-core (unchanged, verified) -------------
__global__ __launch_bounds__(256,1) void attention(const float* __restrict__ Q,
                                                   const float* __restrict__ K,
                                                   const float* __restrict__ V,
                                                   const float* __restrict__ bias,
                                                   float* __restrict__ out){
    extern __shared__ float smA[];
    float* Ks = smA;                      // 200*64
    float* Vt = smA + NK*HD;              // 64*204
    float* Ps = Vt + HD*SP;               // 8*16*204

    const int b = blockIdx.x / NHEAD, h = blockIdx.x % NHEAD;
    const int tid = threadIdx.x, wid = tid >> 5, lane = tid & 31;
    const int g = lane >> 2, tg = lane & 3;

    const float* Kb = K + (size_t)(b*SEQ)*HID + h*HD;
    const float* Vb = V + (size_t)(b*SEQ)*HID + h*HD;
    const float* Qb = Q + (size_t)(b*SEQ)*HID + h*HD;

    for(int v = tid; v < NK*16; v += 256){
        int s = v >> 4, t = v & 15;
        float4 kk = make_float4(0,0,0,0);
        if(s < SEQ) kk = *(const float4*)(Kb + (size_t)s*HID + 4*t);
        float* d = Ks + s*HD + 4*(t ^ (s & 7));
        d[0]=f2tf(kk.x); d[1]=f2tf(kk.y); d[2]=f2tf(kk.z); d[3]=f2tf(kk.w);
    }
    for(int v = tid; v < NK*HD; v += 256){
        int s = v >> 6, d = v & 63;
        float val = (s < SEQ) ? Vb[(size_t)s*HID + d] : 0.f;
        Vt[d*SP + s] = f2tf(val);
    }
    __syncthreads();

    const float* bh = bias + (size_t)h*SEQ*BPITCH;
    float* Pw = Ps + wid*16*SP;

    for(int tile = wid; tile < 13; tile += 8){
        const int q0 = tile*16;
        const int row0 = q0 + g, row1 = q0 + 8 + g;
        const int r0c = row0 < SEQ ? row0 : SEQ-1;
        const int r1c = row1 < SEQ ? row1 : SEQ-1;

        uint32_t aq[8][4];
        {
            const float* Q0 = Qb + (size_t)r0c*HID;
            const float* Q1 = Qb + (size_t)r1c*HID;
            #pragma unroll
            for(int ks=0; ks<8; ks++){
                aq[ks][0] = f2tfu(Q0[8*ks+tg  ] * 0.125f);
                aq[ks][1] = f2tfu(Q1[8*ks+tg  ] * 0.125f);
                aq[ks][2] = f2tfu(Q0[8*ks+tg+4] * 0.125f);
                aq[ks][3] = f2tfu(Q1[8*ks+tg+4] * 0.125f);
            }
        }

        float s[25][4];
        #pragma unroll
        for(int nt=0;nt<25;nt++){ s[nt][0]=0.f; s[nt][1]=0.f; s[nt][2]=0.f; s[nt][3]=0.f; }

        #pragma unroll
        for(int nt=0; nt<25; nt++){
            const float* kr = Ks + (8*nt + g)*HD;
            #pragma unroll
            for(int ks=0; ks<8; ks++){
                uint32_t bb[2];
                bb[0] = __float_as_uint(kr[4*((2*ks  ) ^ g) + tg]);
                bb[1] = __float_as_uint(kr[4*((2*ks+1) ^ g) + tg]);
                mma8(s[nt], aq[ks], bb);
            }
        }

        const float* b0p = bh + (size_t)r0c*BPITCH;
        const float* b1p = bh + (size_t)r1c*BPITCH;
        #pragma unroll
        for(int nt=0; nt<25; nt++){
            int c = 8*nt + 2*tg;
            float2 bv0 = *(const float2*)(b0p + c);
            float2 bv1 = *(const float2*)(b1p + c);
            s[nt][0] += bv0.x; s[nt][1] += bv0.y;
            s[nt][2] += bv1.x; s[nt][3] += bv1.y;
            if(c   >= SEQ){ s[nt][0] = -1e30f; s[nt][2] = -1e30f; }
            if(c+1 >= SEQ){ s[nt][1] = -1e30f; s[nt][3] = -1e30f; }
        }

        float m0 = -1e30f, m1 = -1e30f;
        #pragma unroll
        for(int nt=0; nt<25; nt++){
            m0 = fmaxf(m0, fmaxf(s[nt][0], s[nt][1]));
            m1 = fmaxf(m1, fmaxf(s[nt][2], s[nt][3]));
        }
        #pragma unroll
        for(int o=1;o<4;o<<=1){
            m0 = fmaxf(m0, __shfl_xor_sync(0xffffffffu, m0, o));
            m1 = fmaxf(m1, __shfl_xor_sync(0xffffffffu, m1, o));
        }
        float z0 = 0.f, z1 = 0.f;
        #pragma unroll
        for(int nt=0; nt<25; nt++){
            s[nt][0] = __expf(s[nt][0] - m0);
            s[nt][1] = __expf(s[nt][1] - m0);
            s[nt][2] = __expf(s[nt][2] - m1);
            s[nt][3] = __expf(s[nt][3] - m1);
            z0 += s[nt][0] + s[nt][1];
            z1 += s[nt][2] + s[nt][3];
        }
        #pragma unroll
        for(int o=1;o<4;o<<=1){
            z0 += __shfl_xor_sync(0xffffffffu, z0, o);
            z1 += __shfl_xor_sync(0xffffffffu, z1, o);
        }
        const float inv0 = 1.0f / z0, inv1 = 1.0f / z1;

        #pragma unroll
        for(int nt=0; nt<25; nt++){
            int c = 8*nt + 2*tg;
            float2 p0 = make_float2(f2tf(s[nt][0]*inv0), f2tf(s[nt][1]*inv0));
            float2 p1 = make_float2(f2tf(s[nt][2]*inv1), f2tf(s[nt][3]*inv1));
            *(float2*)(Pw + g*SP + c)     = p0;
            *(float2*)(Pw + (g+8)*SP + c) = p1;
        }
        __syncwarp();

        float o[8][4];
        #pragma unroll
        for(int nt=0;nt<8;nt++){ o[nt][0]=0.f; o[nt][1]=0.f; o[nt][2]=0.f; o[nt][3]=0.f; }

        #pragma unroll
        for(int ks=0; ks<25; ks++){
            uint32_t a[4];
            a[0] = __float_as_uint(Pw[g*SP     + 8*ks + tg    ]);
            a[1] = __float_as_uint(Pw[(g+8)*SP + 8*ks + tg    ]);
            a[2] = __float_as_uint(Pw[g*SP     + 8*ks + tg + 4]);
            a[3] = __float_as_uint(Pw[(g+8)*SP + 8*ks + tg + 4]);
            #pragma unroll
            for(int nt=0; nt<8; nt++){
                const float* vr = Vt + (8*nt + g)*SP + 8*ks;
                uint32_t bb[2];
                bb[0] = __float_as_uint(vr[tg    ]);
                bb[1] = __float_as_uint(vr[tg + 4]);
                mma8(o[nt], a, bb);
            }
        }

        #pragma unroll
        for(int nt=0; nt<8; nt++){
            int c = h*HD + 8*nt + 2*tg;
            if(row0 < SEQ)
                *(float2*)(out + (size_t)(b*SEQ + row0)*HID + c) = make_float2(o[nt][0], o[nt][1]);
            if(row1 < SEQ)
                *(float2*)(out + (size_t)(b*SEQ + row1)*HID + c) = make_float2(o[nt][2], o[nt][3]);
        }
        __syncwarp();
    }
}

// ---------------- launch ------------------------------------------------------
extern "C" void kernel_launch(void* const* d_in, const int* in_sizes, int n_in,
                              void* d_out, int out_size){
    const float* hs    = (const float*)d_in[0];
    const float* wq    = (const float*)d_in[1];
    const float* bq    = (const float*)d_in[2];
    const float* wk    = (const float*)d_in[3];
    const float* wv    = (const float*)d_in[4];
    const float* bv    = (const float*)d_in[5];
    const float* table = (const float*)d_in[6];

    float *q, *k, *v, *bias;
    cudaGetSymbolAddress((void**)&q,    g_q);
    cudaGetSymbolAddress((void**)&k,    g_k);
    cudaGetSymbolAddress((void**)&v,    g_v);
    cudaGetSymbolAddress((void**)&bias, g_bias);

    const int attn_smem = (NK*HD + HD*SP + 8*16*SP) * (int)sizeof(float);  // 207,872 B
    cudaFuncSetAttribute(attention, cudaFuncAttributeMaxDynamicSharedMemorySize, attn_smem);
    cudaFuncSetAttribute(qkv_gemm,  cudaFuncAttributeMaxDynamicSharedMemorySize, GEMM_SMEM);

    build_bias<<<(SEQ*SEQ + 255) / 256, 256>>>(table, bias);

    dim3 gg((MTOT + BM - 1) / BM, HID / BN);   // 99 x 6
    qkv_gemm<<<gg, 128, GEMM_SMEM>>>(hs, wq, bq,      q);
    qkv_gemm<<<gg, 128, GEMM_SMEM>>>(hs, wk, nullptr, k);
    qkv_gemm<<<gg, 128, GEMM_SMEM>>>(hs, wv, bv,      v);

    attention<<<BATCH*NHEAD, 256, attn_smem>>>(q, k, v, bias, (float*)d_out);
}

// round 12
// speedup vs baseline: 3.7108x; 1.0609x over previous
#include <cuda_runtime.h>
#include <cstdint>

#define SEQ    197
#define BATCH  64
#define HID    768
#define NHEAD  12
#define HD     64
#define MTOT   (BATCH*SEQ)      // 12608
#define NUMREL 732
#define NK     200
#define SP     204
#define BPITCH 200

// ---------------- scratch -----------------------------------------------------
__device__ float g_q[MTOT*HID];
__device__ float g_k[MTOT*HID];
__device__ float g_v[MTOT*HID];
__device__ float g_bias[NHEAD*SEQ*BPITCH];
__device__ float g_atf[MTOT*HID];        // hidden_states pre-converted to tf32
__device__ float g_wtf[3*HID*HID];       // wq,wk,wv pre-converted to tf32

// ---------------- helpers ----------------------------------------------------
__device__ __forceinline__ float f2tf(float f){
    uint32_t u; asm("cvt.rna.tf32.f32 %0, %1;" : "=r"(u) : "f"(f));
    return __uint_as_float(u);
}
__device__ __forceinline__ uint32_t f2tfu(float f){
    uint32_t u; asm("cvt.rna.tf32.f32 %0, %1;" : "=r"(u) : "f"(f));
    return u;
}
__device__ __forceinline__ void mma8(float* d, const uint32_t* a, const uint32_t* b){
    asm volatile("mma.sync.aligned.m16n8k8.row.col.f32.tf32.tf32.f32 "
        "{%0,%1,%2,%3}, {%4,%5,%6,%7}, {%8,%9}, {%0,%1,%2,%3};"
        : "+f"(d[0]), "+f"(d[1]), "+f"(d[2]), "+f"(d[3])
        : "r"(a[0]), "r"(a[1]), "r"(a[2]), "r"(a[3]), "r"(b[0]), "r"(b[1]));
}
__device__ __forceinline__ void cpa16(uint32_t dst, const void* src){
    asm volatile("cp.async.cg.shared.global [%0], [%1], 16;" :: "r"(dst), "l"(src));
}
__device__ __forceinline__ void cpcommit(){ asm volatile("cp.async.commit_group;"); }
template<int N> __device__ __forceinline__ void cpwait(){
    asm volatile("cp.async.wait_group %0;" :: "n"(N));
}

// ---------------- tf32 pre-conversion (bandwidth-bound) -----------------------
__global__ __launch_bounds__(256) void conv_tf32(const float* __restrict__ src,
                                                 float* __restrict__ dst, int n4){
    int i = blockIdx.x * blockDim.x + threadIdx.x;
    if(i >= n4) return;
    float4 v = ((const float4*)src)[i];
    v.x = f2tf(v.x); v.y = f2tf(v.y); v.z = f2tf(v.z); v.w = f2tf(v.w);
    ((float4*)dst)[i] = v;
}

// ---------------- QKV GEMM v4: fused 3-in-1, pre-converted tf32 ---------------
// z=0:Q(+bq) z=1:K z=2:V(+bv). Block 128x128, 128 thr, 64x64 warp tiles, cp.async.
#define BM 128
#define BN 128
#define BK 16
#define APITCH 20
#define WPITCH 136
#define ASLOT (BM*APITCH)
#define WSLOT (BK*WPITCH)
#define GEMM_SMEM (3*(ASLOT+WSLOT)*4)   // 56,832 B

__global__ __launch_bounds__(128,2) void qkv_gemm(const float* __restrict__ bq,
                                                  const float* __restrict__ bv){
    extern __shared__ float sm[];
    float* Asb = sm;
    float* Wsb = sm + 3*ASLOT;

    const int z = blockIdx.z;
    const float* A = g_atf;
    const float* W = g_wtf + (size_t)z*HID*HID;
    const float* bias = (z == 0) ? bq : (z == 2 ? bv : nullptr);
    float* C = (z == 0) ? g_q : (z == 1 ? g_k : g_v);

    const int bm = blockIdx.x * BM, bn = blockIdx.y * BN;
    const int tid = threadIdx.x, wid = tid >> 5, lane = tid & 31;
    const int wm = (wid & 1) * 64, wn = (wid >> 1) * 64;
    const int g = lane >> 2, tg = lane & 3;

    const uint32_t sbase = (uint32_t)__cvta_generic_to_shared(sm);

    auto stage = [&](int slot, int kc){
        const int k0 = kc * BK;
        #pragma unroll
        for(int i=0;i<4;i++){
            int v = tid + i*128;
            int r = v >> 2, c = (v & 3) * 4;
            int grow = bm + r; if(grow >= MTOT) grow = MTOT-1;
            cpa16(sbase + (uint32_t)(slot*ASLOT + r*APITCH + c)*4u,
                  A + (size_t)grow*HID + k0 + c);
        }
        #pragma unroll
        for(int i=0;i<4;i++){
            int v = tid + i*128;
            int r = v >> 5, c = (v & 31) * 4;
            cpa16(sbase + (uint32_t)(3*ASLOT + slot*WSLOT + r*WPITCH + c)*4u,
                  W + (size_t)(k0+r)*HID + bn + c);
        }
    };

    float acc[4][8][4] = {};

    stage(0,0); cpcommit();
    stage(1,1); cpcommit();

    const int NC = HID / BK;   // 48
    for(int i=0;i<NC;i++){
        cpwait<1>();
        __syncthreads();
        if(i+2 < NC) stage((i+2)%3, i+2);
        cpcommit();

        const float* Ab = Asb + (i%3)*ASLOT;
        const float* Wb = Wsb + (i%3)*WSLOT;

        #pragma unroll
        for(int kk=0; kk<BK; kk+=8){
            uint32_t af[4][4], bf[8][2];
            #pragma unroll
            for(int mi=0;mi<4;mi++){
                const float* ap = Ab + (wm + mi*16 + g)*APITCH + kk + tg;
                af[mi][0] = __float_as_uint(ap[0]);
                af[mi][1] = __float_as_uint(ap[8*APITCH]);
                af[mi][2] = __float_as_uint(ap[4]);
                af[mi][3] = __float_as_uint(ap[8*APITCH+4]);
            }
            #pragma unroll
            for(int ni=0;ni<8;ni++){
                const float* wp = Wb + (kk+tg)*WPITCH + wn + ni*8 + g;
                bf[ni][0] = __float_as_uint(wp[0]);
                bf[ni][1] = __float_as_uint(wp[4*WPITCH]);
            }
            #pragma unroll
            for(int mi=0;mi<4;mi++)
                #pragma unroll
                for(int ni=0;ni<8;ni++)
                    mma8(acc[mi][ni], af[mi], bf[ni]);
        }
    }

    #pragma unroll
    for(int mi=0;mi<4;mi++){
        #pragma unroll
        for(int ni=0;ni<8;ni++){
            int col = bn + wn + ni*8 + tg*2;
            float b0 = bias ? bias[col]   : 0.f;
            float b1 = bias ? bias[col+1] : 0.f;
            int r0 = bm + wm + mi*16 + g;
            if(r0 < MTOT)
                *(float2*)(C + (size_t)r0*HID + col) = make_float2(acc[mi][ni][0]+b0, acc[mi][ni][1]+b1);
            int r1 = r0 + 8;
            if(r1 < MTOT)
                *(float2*)(C + (size_t)r1*HID + col) = make_float2(acc[mi][ni][2]+b0, acc[mi][ni][3]+b1);
        }
    }
}

// ---------------- relative position bias (pitch 200) --------------------------
__global__ void build_bias(const float* __restrict__ table, float* __restrict__ bias){
    int qk = blockIdx.x * blockDim.x + threadIdx.x;
    if(qk >= SEQ*SEQ) return;
    int q = qk / SEQ, k = qk % SEQ;
    int idx;
    if(q == 0 && k == 0)      idx = NUMREL - 1;
    else if(q == 0)           idx = NUMREL - 3;
    else if(k == 0)           idx = NUMREL - 2;
    else {
        int i = q - 1, j = k - 1;
        int hi = i / 14, wi = i % 14;
        int hj = j / 14, wj = j % 14;
        idx = (hi - hj + 13) * 27 + (wi - wj + 13);
    }
    #pragma unroll
    for(int h = 0; h < NHEAD; h++)
        bias[(size_t)h*SEQ*BPITCH + q*BPITCH + k] = table[idx*NHEAD + h];
}

// ---------------- attention v4: tensor-core (unchanged, verified) -------------
__global__ __launch_bounds__(256,1) void attention(const float* __restrict__ Q,
                                                   const float* __restrict__ K,
                                                   const float* __restrict__ V,
                                                   const float* __restrict__ bias,
                                                   float* __restrict__ out){
    extern __shared__ float smA[];
    float* Ks = smA;                      // 200*64
    float* Vt = smA + NK*HD;              // 64*204
    float* Ps = Vt + HD*SP;               // 8*16*204

    const int b = blockIdx.x / NHEAD, h = blockIdx.x % NHEAD;
    const int tid = threadIdx.x, wid = tid >> 5, lane = tid & 31;
    const int g = lane >> 2, tg = lane & 3;

    const float* Kb = K + (size_t)(b*SEQ)*HID + h*HD;
    const float* Vb = V + (size_t)(b*SEQ)*HID + h*HD;
    const float* Qb = Q + (size_t)(b*SEQ)*HID + h*HD;

    for(int v = tid; v < NK*16; v += 256){
        int s = v >> 4, t = v & 15;
        float4 kk = make_float4(0,0,0,0);
        if(s < SEQ) kk = *(const float4*)(Kb + (size_t)s*HID + 4*t);
        float* d = Ks + s*HD + 4*(t ^ (s & 7));
        d[0]=f2tf(kk.x); d[1]=f2tf(kk.y); d[2]=f2tf(kk.z); d[3]=f2tf(kk.w);
    }
    for(int v = tid; v < NK*HD; v += 256){
        int s = v >> 6, d = v & 63;
        float val = (s < SEQ) ? Vb[(size_t)s*HID + d] : 0.f;
        Vt[d*SP + s] = f2tf(val);
    }
    __syncthreads();

    const float* bh = bias + (size_t)h*SEQ*BPITCH;
    float* Pw = Ps + wid*16*SP;

    for(int tile = wid; tile < 13; tile += 8){
        const int q0 = tile*16;
        const int row0 = q0 + g, row1 = q0 + 8 + g;
        const int r0c = row0 < SEQ ? row0 : SEQ-1;
        const int r1c = row1 < SEQ ? row1 : SEQ-1;

        uint32_t aq[8][4];
        {
            const float* Q0 = Qb + (size_t)r0c*HID;
            const float* Q1 = Qb + (size_t)r1c*HID;
            #pragma unroll
            for(int ks=0; ks<8; ks++){
                aq[ks][0] = f2tfu(Q0[8*ks+tg  ] * 0.125f);
                aq[ks][1] = f2tfu(Q1[8*ks+tg  ] * 0.125f);
                aq[ks][2] = f2tfu(Q0[8*ks+tg+4] * 0.125f);
                aq[ks][3] = f2tfu(Q1[8*ks+tg+4] * 0.125f);
            }
        }

        float s[25][4];
        #pragma unroll
        for(int nt=0;nt<25;nt++){ s[nt][0]=0.f; s[nt][1]=0.f; s[nt][2]=0.f; s[nt][3]=0.f; }

        #pragma unroll
        for(int nt=0; nt<25; nt++){
            const float* kr = Ks + (8*nt + g)*HD;
            #pragma unroll
            for(int ks=0; ks<8; ks++){
                uint32_t bb[2];
                bb[0] = __float_as_uint(kr[4*((2*ks  ) ^ g) + tg]);
                bb[1] = __float_as_uint(kr[4*((2*ks+1) ^ g) + tg]);
                mma8(s[nt], aq[ks], bb);
            }
        }

        const float* b0p = bh + (size_t)r0c*BPITCH;
        const float* b1p = bh + (size_t)r1c*BPITCH;
        #pragma unroll
        for(int nt=0; nt<25; nt++){
            int c = 8*nt + 2*tg;
            float2 bv0 = *(const float2*)(b0p + c);
            float2 bv1 = *(const float2*)(b1p + c);
            s[nt][0] += bv0.x; s[nt][1] += bv0.y;
            s[nt][2] += bv1.x; s[nt][3] += bv1.y;
            if(c   >= SEQ){ s[nt][0] = -1e30f; s[nt][2] = -1e30f; }
            if(c+1 >= SEQ){ s[nt][1] = -1e30f; s[nt][3] = -1e30f; }
        }

        float m0 = -1e30f, m1 = -1e30f;
        #pragma unroll
        for(int nt=0; nt<25; nt++){
            m0 = fmaxf(m0, fmaxf(s[nt][0], s[nt][1]));
            m1 = fmaxf(m1, fmaxf(s[nt][2], s[nt][3]));
        }
        #pragma unroll
        for(int o=1;o<4;o<<=1){
            m0 = fmaxf(m0, __shfl_xor_sync(0xffffffffu, m0, o));
            m1 = fmaxf(m1, __shfl_xor_sync(0xffffffffu, m1, o));
        }
        float z0 = 0.f, z1 = 0.f;
        #pragma unroll
        for(int nt=0; nt<25; nt++){
            s[nt][0] = __expf(s[nt][0] - m0);
            s[nt][1] = __expf(s[nt][1] - m0);
            s[nt][2] = __expf(s[nt][2] - m1);
            s[nt][3] = __expf(s[nt][3] - m1);
            z0 += s[nt][0] + s[nt][1];
            z1 += s[nt][2] + s[nt][3];
        }
        #pragma unroll
        for(int o=1;o<4;o<<=1){
            z0 += __shfl_xor_sync(0xffffffffu, z0, o);
            z1 += __shfl_xor_sync(0xffffffffu, z1, o);
        }
        const float inv0 = 1.0f / z0, inv1 = 1.0f / z1;

        #pragma unroll
        for(int nt=0; nt<25; nt++){
            int c = 8*nt + 2*tg;
            float2 p0 = make_float2(f2tf(s[nt][0]*inv0), f2tf(s[nt][1]*inv0));
            float2 p1 = make_float2(f2tf(s[nt][2]*inv1), f2tf(s[nt][3]*inv1));
            *(float2*)(Pw + g*SP + c)     = p0;
            *(float2*)(Pw + (g+8)*SP + c) = p1;
        }
        __syncwarp();

        float o[8][4];
        #pragma unroll
        for(int nt=0;nt<8;nt++){ o[nt][0]=0.f; o[nt][1]=0.f; o[nt][2]=0.f; o[nt][3]=0.f; }

        #pragma unroll
        for(int ks=0; ks<25; ks++){
            uint32_t a[4];
            a[0] = __float_as_uint(Pw[g*SP     + 8*ks + tg    ]);
            a[1] = __float_as_uint(Pw[(g+8)*SP + 8*ks + tg    ]);
            a[2] = __float_as_uint(Pw[g*SP     + 8*ks + tg + 4]);
            a[3] = __float_as_uint(Pw[(g+8)*SP + 8*ks + tg + 4]);
            #pragma unroll
            for(int nt=0; nt<8; nt++){
                const float* vr = Vt + (8*nt + g)*SP + 8*ks;
                uint32_t bb[2];
                bb[0] = __float_as_uint(vr[tg    ]);
                bb[1] = __float_as_uint(vr[tg + 4]);
                mma8(o[nt], a, bb);
            }
        }

        #pragma unroll
        for(int nt=0; nt<8; nt++){
            int c = h*HD + 8*nt + 2*tg;
            if(row0 < SEQ)
                *(float2*)(out + (size_t)(b*SEQ + row0)*HID + c) = make_float2(o[nt][0], o[nt][1]);
            if(row1 < SEQ)
                *(float2*)(out + (size_t)(b*SEQ + row1)*HID + c) = make_float2(o[nt][2], o[nt][3]);
        }
        __syncwarp();
    }
}

// ---------------- launch ------------------------------------------------------
extern "C" void kernel_launch(void* const* d_in, const int* in_sizes, int n_in,
                              void* d_out, int out_size){
    const float* hs    = (const float*)d_in[0];
    const float* wq    = (const float*)d_in[1];
    const float* bq    = (const float*)d_in[2];
    const float* wk    = (const float*)d_in[3];
    const float* wv    = (const float*)d_in[4];
    const float* bv    = (const float*)d_in[5];
    const float* table = (const float*)d_in[6];

    float *q, *k, *v, *bias, *atf, *wtf;
    cudaGetSymbolAddress((void**)&q,    g_q);
    cudaGetSymbolAddress((void**)&k,    g_k);
    cudaGetSymbolAddress((void**)&v,    g_v);
    cudaGetSymbolAddress((void**)&bias, g_bias);
    cudaGetSymbolAddress((void**)&atf,  g_atf);
    cudaGetSymbolAddress((void**)&wtf,  g_wtf);

    const int attn_smem = (NK*HD + HD*SP + 8*16*SP) * (int)sizeof(float);  // 207,872 B
    cudaFuncSetAttribute(attention, cudaFuncAttributeMaxDynamicSharedMemorySize, attn_smem);
    cudaFuncSetAttribute(qkv_gemm,  cudaFuncAttributeMaxDynamicSharedMemorySize, GEMM_SMEM);

    // pre-convert inputs to tf32 (RNA) — numerics identical to in-loop cvt
    const int a4 = MTOT*HID/4, w4 = HID*HID/4;
    conv_tf32<<<(a4 + 255)/256, 256>>>(hs, atf, a4);
    conv_tf32<<<(w4 + 255)/256, 256>>>(wq, wtf,           w4);
    conv_tf32<<<(w4 + 255)/256, 256>>>(wk, wtf +   HID*HID, w4);
    conv_tf32<<<(w4 + 255)/256, 256>>>(wv, wtf + 2*HID*HID, w4);

    build_bias<<<(SEQ*SEQ + 255) / 256, 256>>>(table, bias);

    dim3 gg((MTOT + BM - 1) / BM, HID / BN, 3);   // 99 x 6 x 3
    qkv_gemm<<<gg, 128, GEMM_SMEM>>>(bq, bv);

    attention<<<BATCH*NHEAD, 256, attn_smem>>>(q, k, v, bias, (float*)d_out);
}

// round 14
// speedup vs baseline: 4.0674x; 1.0961x over previous
#include <cuda_runtime.h>
#include <cstdint>

#define SEQ    197
#define BATCH  64
#define HID    768
#define NHEAD  12
#define HD     64
#define MTOT   (BATCH*SEQ)      // 12608
#define NUMREL 732
#define NK     200
#define SP     204
#define BPITCH 200
#define PBP    12               // bounce buffer pitch (12g+tg mod 32 all-distinct)
#define PBUFW  (2*16*PBP)       // 384 floats per warp (ping-pong)

// ---------------- scratch -----------------------------------------------------
__device__ float g_q[MTOT*HID];
__device__ float g_k[MTOT*HID];
__device__ float g_v[MTOT*HID];
__device__ float g_bias[NHEAD*SEQ*BPITCH];
__device__ float g_atf[MTOT*HID];
__device__ float g_wtf[3*HID*HID];

// ---------------- helpers ----------------------------------------------------
__device__ __forceinline__ float f2tf(float f){
    uint32_t u; asm("cvt.rna.tf32.f32 %0, %1;" : "=r"(u) : "f"(f));
    return __uint_as_float(u);
}
__device__ __forceinline__ uint32_t f2tfu(float f){
    uint32_t u; asm("cvt.rna.tf32.f32 %0, %1;" : "=r"(u) : "f"(f));
    return u;
}
__device__ __forceinline__ void mma8(float* d, const uint32_t* a, const uint32_t* b){
    asm volatile("mma.sync.aligned.m16n8k8.row.col.f32.tf32.tf32.f32 "
        "{%0,%1,%2,%3}, {%4,%5,%6,%7}, {%8,%9}, {%0,%1,%2,%3};"
        : "+f"(d[0]), "+f"(d[1]), "+f"(d[2]), "+f"(d[3])
        : "r"(a[0]), "r"(a[1]), "r"(a[2]), "r"(a[3]), "r"(b[0]), "r"(b[1]));
}
__device__ __forceinline__ void cpa16(uint32_t dst, const void* src){
    asm volatile("cp.async.cg.shared.global [%0], [%1], 16;" :: "r"(dst), "l"(src));
}
__device__ __forceinline__ void cpcommit(){ asm volatile("cp.async.commit_group;"); }
template<int N> __device__ __forceinline__ void cpwait(){
    asm volatile("cp.async.wait_group %0;" :: "n"(N));
}

// ---------------- tf32 pre-conversion -----------------------------------------
__global__ __launch_bounds__(256) void conv_tf32(const float* __restrict__ src,
                                                 float* __restrict__ dst, int n4){
    int i = blockIdx.x * blockDim.x + threadIdx.x;
    if(i >= n4) return;
    float4 v = ((const float4*)src)[i];
    v.x = f2tf(v.x); v.y = f2tf(v.y); v.z = f2tf(v.z); v.w = f2tf(v.w);
    ((float4*)dst)[i] = v;
}

// ---------------- QKV GEMM v4 (unchanged, verified) ---------------------------
#define BM 128
#define BN 128
#define BK 16
#define APITCH 20
#define WPITCH 136
#define ASLOT (BM*APITCH)
#define WSLOT (BK*WPITCH)
#define GEMM_SMEM (3*(ASLOT+WSLOT)*4)   // 56,832 B

__global__ __launch_bounds__(128,2) void qkv_gemm(const float* __restrict__ bq,
                                                  const float* __restrict__ bv){
    extern __shared__ float sm[];
    float* Asb = sm;
    float* Wsb = sm + 3*ASLOT;

    const int z = blockIdx.z;
    const float* A = g_atf;
    const float* W = g_wtf + (size_t)z*HID*HID;
    const float* bias = (z == 0) ? bq : (z == 2 ? bv : nullptr);
    float* C = (z == 0) ? g_q : (z == 1 ? g_k : g_v);

    const int bm = blockIdx.x * BM, bn = blockIdx.y * BN;
    const int tid = threadIdx.x, wid = tid >> 5, lane = tid & 31;
    const int wm = (wid & 1) * 64, wn = (wid >> 1) * 64;
    const int g = lane >> 2, tg = lane & 3;

    const uint32_t sbase = (uint32_t)__cvta_generic_to_shared(sm);

    auto stage = [&](int slot, int kc){
        const int k0 = kc * BK;
        #pragma unroll
        for(int i=0;i<4;i++){
            int v = tid + i*128;
            int r = v >> 2, c = (v & 3) * 4;
            int grow = bm + r; if(grow >= MTOT) grow = MTOT-1;
            cpa16(sbase + (uint32_t)(slot*ASLOT + r*APITCH + c)*4u,
                  A + (size_t)grow*HID + k0 + c);
        }
        #pragma unroll
        for(int i=0;i<4;i++){
            int v = tid + i*128;
            int r = v >> 5, c = (v & 31) * 4;
            cpa16(sbase + (uint32_t)(3*ASLOT + slot*WSLOT + r*WPITCH + c)*4u,
                  W + (size_t)(k0+r)*HID + bn + c);
        }
    };

    float acc[4][8][4] = {};

    stage(0,0); cpcommit();
    stage(1,1); cpcommit();

    const int NC = HID / BK;   // 48
    for(int i=0;i<NC;i++){
        cpwait<1>();
        __syncthreads();
        if(i+2 < NC) stage((i+2)%3, i+2);
        cpcommit();

        const float* Ab = Asb + (i%3)*ASLOT;
        const float* Wb = Wsb + (i%3)*WSLOT;

        #pragma unroll
        for(int kk=0; kk<BK; kk+=8){
            uint32_t af[4][4], bf[8][2];
            #pragma unroll
            for(int mi=0;mi<4;mi++){
                const float* ap = Ab + (wm + mi*16 + g)*APITCH + kk + tg;
                af[mi][0] = __float_as_uint(ap[0]);
                af[mi][1] = __float_as_uint(ap[8*APITCH]);
                af[mi][2] = __float_as_uint(ap[4]);
                af[mi][3] = __float_as_uint(ap[8*APITCH+4]);
            }
            #pragma unroll
            for(int ni=0;ni<8;ni++){
                const float* wp = Wb + (kk+tg)*WPITCH + wn + ni*8 + g;
                bf[ni][0] = __float_as_uint(wp[0]);
                bf[ni][1] = __float_as_uint(wp[4*WPITCH]);
            }
            #pragma unroll
            for(int mi=0;mi<4;mi++)
                #pragma unroll
                for(int ni=0;ni<8;ni++)
                    mma8(acc[mi][ni], af[mi], bf[ni]);
        }
    }

    #pragma unroll
    for(int mi=0;mi<4;mi++){
        #pragma unroll
        for(int ni=0;ni<8;ni++){
            int col = bn + wn + ni*8 + tg*2;
            float b0 = bias ? bias[col]   : 0.f;
            float b1 = bias ? bias[col+1] : 0.f;
            int r0 = bm + wm + mi*16 + g;
            if(r0 < MTOT)
                *(float2*)(C + (size_t)r0*HID + col) = make_float2(acc[mi][ni][0]+b0, acc[mi][ni][1]+b1);
            int r1 = r0 + 8;
            if(r1 < MTOT)
                *(float2*)(C + (size_t)r1*HID + col) = make_float2(acc[mi][ni][2]+b0, acc[mi][ni][3]+b1);
        }
    }
}

// ---------------- relative position bias (pitch 200) --------------------------
__global__ void build_bias(const float* __restrict__ table, float* __restrict__ bias){
    int qk = blockIdx.x * blockDim.x + threadIdx.x;
    if(qk >= SEQ*SEQ) return;
    int q = qk / SEQ, k = qk % SEQ;
    int idx;
    if(q == 0 && k == 0)      idx = NUMREL - 1;
    else if(q == 0)           idx = NUMREL - 3;
    else if(k == 0)           idx = NUMREL - 2;
    else {
        int i = q - 1, j = k - 1;
        int hi = i / 14, wi = i % 14;
        int hj = j / 14, wj = j % 14;
        idx = (hi - hj + 13) * 27 + (wi - wj + 13);
    }
    #pragma unroll
    for(int h = 0; h < NHEAD; h++)
        bias[(size_t)h*SEQ*BPITCH + q*BPITCH + k] = table[idx*NHEAD + h];
}

// ---------------- attention v5: 512 thr, online-softmax chunks, no Ps ---------
#define ATTN_SMEM ((NK*HD + HD*SP + 16*PBUFW)*4)   // 128,000 B

__global__ __launch_bounds__(512,1) void attention(const float* __restrict__ Q,
                                                   const float* __restrict__ K,
                                                   const float* __restrict__ V,
                                                   const float* __restrict__ bias,
                                                   float* __restrict__ out){
    extern __shared__ float smA[];
    float* Ks = smA;                      // 200*64 swizzled tf32
    float* Vt = smA + NK*HD;              // 64*204 transposed tf32
    float* Pb = Vt + HD*SP;               // 16 warps * 384 bounce

    const int b = blockIdx.x / NHEAD, h = blockIdx.x % NHEAD;
    const int tid = threadIdx.x, wid = tid >> 5, lane = tid & 31;
    const int g = lane >> 2, tg = lane & 3;

    const float* Kb = K + (size_t)(b*SEQ)*HID + h*HD;
    const float* Vb = V + (size_t)(b*SEQ)*HID + h*HD;
    const float* Qb = Q + (size_t)(b*SEQ)*HID + h*HD;

    for(int v = tid; v < NK*16; v += 512){
        int s = v >> 4, t = v & 15;
        float4 kk = make_float4(0,0,0,0);
        if(s < SEQ) kk = *(const float4*)(Kb + (size_t)s*HID + 4*t);
        float* d = Ks + s*HD + 4*(t ^ (s & 7));
        d[0]=f2tf(kk.x); d[1]=f2tf(kk.y); d[2]=f2tf(kk.z); d[3]=f2tf(kk.w);
    }
    for(int v = tid; v < NK*HD; v += 512){
        int s = v >> 6, d = v & 63;
        float val = (s < SEQ) ? Vb[(size_t)s*HID + d] : 0.f;
        Vt[d*SP + s] = f2tf(val);
    }
    __syncthreads();

    if(wid < 13){
        const int q0 = wid*16;
        const int row0 = q0 + g, row1 = q0 + 8 + g;
        const int r0c = row0 < SEQ ? row0 : SEQ-1;
        const int r1c = row1 < SEQ ? row1 : SEQ-1;

        // Q fragments (pre-scaled, tf32)
        uint32_t aq[8][4];
        {
            const float* Q0 = Qb + (size_t)r0c*HID;
            const float* Q1 = Qb + (size_t)r1c*HID;
            #pragma unroll
            for(int ks=0; ks<8; ks++){
                aq[ks][0] = f2tfu(Q0[8*ks+tg  ] * 0.125f);
                aq[ks][1] = f2tfu(Q1[8*ks+tg  ] * 0.125f);
                aq[ks][2] = f2tfu(Q0[8*ks+tg+4] * 0.125f);
                aq[ks][3] = f2tfu(Q1[8*ks+tg+4] * 0.125f);
            }
        }

        const float* b0p = bias + (size_t)h*SEQ*BPITCH + (size_t)r0c*BPITCH;
        const float* b1p = bias + (size_t)h*SEQ*BPITCH + (size_t)r1c*BPITCH;
        float* myP = Pb + wid*PBUFW;

        float o[8][4] = {};
        float m0 = -1e30f, m1 = -1e30f, z0 = 0.f, z1 = 0.f;

        #pragma unroll
        for(int cc=0; cc<4; cc++){
            const int CNT  = (cc==0) ? 7 : 6;
            const int BASE = (cc==0) ? 0 : 7 + 6*(cc-1);

            // ---- scores for this chunk ----
            float s[7][4];
            #pragma unroll
            for(int j=0;j<7;j++){ s[j][0]=0.f; s[j][1]=0.f; s[j][2]=0.f; s[j][3]=0.f; }

            #pragma unroll
            for(int j=0;j<CNT;j++){
                const int nt = BASE + j;
                const float* kr = Ks + (8*nt + g)*HD;
                #pragma unroll
                for(int ks=0; ks<8; ks++){
                    uint32_t bb[2];
                    bb[0] = __float_as_uint(kr[4*((2*ks  ) ^ g) + tg]);
                    bb[1] = __float_as_uint(kr[4*((2*ks+1) ^ g) + tg]);
                    mma8(s[j], aq[ks], bb);
                }
            }

            // ---- bias + mask ----
            #pragma unroll
            for(int j=0;j<CNT;j++){
                int c = 8*(BASE+j) + 2*tg;
                float2 bv0 = *(const float2*)(b0p + c);
                float2 bv1 = *(const float2*)(b1p + c);
                s[j][0] += bv0.x; s[j][1] += bv0.y;
                s[j][2] += bv1.x; s[j][3] += bv1.y;
                if(c   >= SEQ){ s[j][0] = -1e30f; s[j][2] = -1e30f; }
                if(c+1 >= SEQ){ s[j][1] = -1e30f; s[j][3] = -1e30f; }
            }

            // ---- online softmax merge ----
            float mc0 = -1e30f, mc1 = -1e30f;
            #pragma unroll
            for(int j=0;j<CNT;j++){
                mc0 = fmaxf(mc0, fmaxf(s[j][0], s[j][1]));
                mc1 = fmaxf(mc1, fmaxf(s[j][2], s[j][3]));
            }
            #pragma unroll
            for(int off=1;off<4;off<<=1){
                mc0 = fmaxf(mc0, __shfl_xor_sync(0xffffffffu, mc0, off));
                mc1 = fmaxf(mc1, __shfl_xor_sync(0xffffffffu, mc1, off));
            }
            float mn0 = fmaxf(m0, mc0), mn1 = fmaxf(m1, mc1);
            float sc0 = __expf(m0 - mn0), sc1 = __expf(m1 - mn1);
            m0 = mn0; m1 = mn1;
            z0 *= sc0; z1 *= sc1;
            #pragma unroll
            for(int nt=0;nt<8;nt++){
                o[nt][0] *= sc0; o[nt][1] *= sc0;
                o[nt][2] *= sc1; o[nt][3] *= sc1;
            }
            #pragma unroll
            for(int j=0;j<CNT;j++){
                s[j][0] = __expf(s[j][0] - m0);
                s[j][1] = __expf(s[j][1] - m0);
                s[j][2] = __expf(s[j][2] - m1);
                s[j][3] = __expf(s[j][3] - m1);
                z0 += s[j][0] + s[j][1];
                z1 += s[j][2] + s[j][3];
            }

            // ---- PV for this chunk (unnormalized P via bounce buffer) ----
            #pragma unroll
            for(int j=0;j<CNT;j++){
                const int ks = BASE + j;
                float* buf = myP + (ks & 1) * (16*PBP);
                *(float2*)(buf + g*PBP     + 2*tg) = make_float2(f2tf(s[j][0]), f2tf(s[j][1]));
                *(float2*)(buf + (g+8)*PBP + 2*tg) = make_float2(f2tf(s[j][2]), f2tf(s[j][3]));
                __syncwarp();
                uint32_t a[4];
                a[0] = __float_as_uint(buf[g*PBP     + tg    ]);
                a[1] = __float_as_uint(buf[(g+8)*PBP + tg    ]);
                a[2] = __float_as_uint(buf[g*PBP     + tg + 4]);
                a[3] = __float_as_uint(buf[(g+8)*PBP + tg + 4]);
                #pragma unroll
                for(int nt=0; nt<8; nt++){
                    const float* vr = Vt + (8*nt + g)*SP + 8*ks;
                    uint32_t bb[2];
                    bb[0] = __float_as_uint(vr[tg    ]);
                    bb[1] = __float_as_uint(vr[tg + 4]);
                    mma8(o[nt], a, bb);
                }
            }
        }

        // ---- finalize: reduce z across quad, scale, store ----
        #pragma unroll
        for(int off=1;off<4;off<<=1){
            z0 += __shfl_xor_sync(0xffffffffu, z0, off);
            z1 += __shfl_xor_sync(0xffffffffu, z1, off);
        }
        const float inv0 = 1.0f / z0, inv1 = 1.0f / z1;

        #pragma unroll
        for(int nt=0; nt<8; nt++){
            int c = h*HD + 8*nt + 2*tg;
            if(row0 < SEQ)
                *(float2*)(out + (size_t)(b*SEQ + row0)*HID + c) =
                    make_float2(o[nt][0]*inv0, o[nt][1]*inv0);
            if(row1 < SEQ)
                *(float2*)(out + (size_t)(b*SEQ + row1)*HID + c) =
                    make_float2(o[nt][2]*inv1, o[nt][3]*inv1);
        }
    }
}

// ---------------- launch ------------------------------------------------------
extern "C" void kernel_launch(void* const* d_in, const int* in_sizes, int n_in,
                              void* d_out, int out_size){
    const float* hs    = (const float*)d_in[0];
    const float* wq    = (const float*)d_in[1];
    const float* bq    = (const float*)d_in[2];
    const float* wk    = (const float*)d_in[3];
    const float* wv    = (const float*)d_in[4];
    const float* bv    = (const float*)d_in[5];
    const float* table = (const float*)d_in[6];

    float *q, *k, *v, *bias, *atf, *wtf;
    cudaGetSymbolAddress((void**)&q,    g_q);
    cudaGetSymbolAddress((void**)&k,    g_k);
    cudaGetSymbolAddress((void**)&v,    g_v);
    cudaGetSymbolAddress((void**)&bias, g_bias);
    cudaGetSymbolAddress((void**)&atf,  g_atf);
    cudaGetSymbolAddress((void**)&wtf,  g_wtf);

    cudaFuncSetAttribute(attention, cudaFuncAttributeMaxDynamicSharedMemorySize, ATTN_SMEM);
    cudaFuncSetAttribute(qkv_gemm,  cudaFuncAttributeMaxDynamicSharedMemorySize, GEMM_SMEM);

    const int a4 = MTOT*HID/4, w4 = HID*HID/4;
    conv_tf32<<<(a4 + 255)/256, 256>>>(hs, atf, a4);
    conv_tf32<<<(w4 + 255)/256, 256>>>(wq, wtf,             w4);
    conv_tf32<<<(w4 + 255)/256, 256>>>(wk, wtf +   HID*HID, w4);
    conv_tf32<<<(w4 + 255)/256, 256>>>(wv, wtf + 2*HID*HID, w4);

    build_bias<<<(SEQ*SEQ + 255) / 256, 256>>>(table, bias);

    dim3 gg((MTOT + BM - 1) / BM, HID / BN, 3);   // 99 x 6 x 3
    qkv_gemm<<<gg, 128, GEMM_SMEM>>>(bq, bv);

    attention<<<BATCH*NHEAD, 512, ATTN_SMEM>>>(q, k, v, bias, (float*)d_out);
}